// round 1
// baseline (speedup 1.0000x reference)
#include <cuda_runtime.h>

// ============================================================================
// Multihead_Attention (no-softmax => fully linear) on sm_100a.
//
// Pipeline (all fp32, f32x2 packed FMA inner loops):
//   Q = x @ q_w^T + q_b        [4096,1024]  (gemm_nt_bias)
//   K = x @ k_w^T + k_b        [4096,1024]
//   V = y @ v_w^T + v_b        [4096,1024]
//   For g in 0..31 (g = head*2 + batch, each = 128 contiguous rows):
//     Mg[64,64] = (1/32) * Kg^T Vg   where Kg = K.rows(g*128..+128).reshape(2048,64)
//   Out.rows(g) = Qblk_g @ blockdiag(Mg)  (apply per 64-col chunk)
//   result = Out @ o_w^T + o_b  [4096,1024]
// ============================================================================

#define MROWS 4096
#define DMODEL 1024

__device__ float g_Q[MROWS * DMODEL];
__device__ float g_K[MROWS * DMODEL];
__device__ float g_V[MROWS * DMODEL];
__device__ float g_O[MROWS * DMODEL];
__device__ float g_M[32 * 64 * 64];

// ---------------- f32x2 packed helpers (Blackwell full-rate fp32) ----------
__device__ __forceinline__ unsigned long long f32x2_dup(float x) {
    unsigned long long r;
    asm("mov.b64 %0, {%1, %1};" : "=l"(r) : "f"(x));
    return r;
}
__device__ __forceinline__ unsigned long long f32x2_pack(float x, float y) {
    unsigned long long r;
    asm("mov.b64 %0, {%1, %2};" : "=l"(r) : "f"(x), "f"(y));
    return r;
}
__device__ __forceinline__ unsigned long long f32x2_fma(unsigned long long a,
                                                        unsigned long long b,
                                                        unsigned long long c) {
    unsigned long long d;
    asm("fma.rn.f32x2 %0, %1, %2, %3;" : "=l"(d) : "l"(a), "l"(b), "l"(c));
    return d;
}
__device__ __forceinline__ float2 f32x2_unpack(unsigned long long v) {
    float2 r;
    asm("mov.b64 {%0, %1}, %2;" : "=f"(r.x), "=f"(r.y) : "l"(v));
    return r;
}

// ============================================================================
// GEMM: C[4096,1024] = A[4096,1024] @ W[1024,1024]^T + bias
// 128x128 tile, BK=16, 256 threads, 8x8 per thread, f32x2 accumulation.
// ============================================================================
__global__ __launch_bounds__(256, 2)
void gemm_nt_bias(const float* __restrict__ A, const float* __restrict__ W,
                  const float* __restrict__ bias, float* __restrict__ C) {
    __shared__ float As[16][132];
    __shared__ float Bs[16][132];

    const int tid = threadIdx.x;
    const int tx = tid & 15;        // -> N (8 cols)
    const int ty = tid >> 4;        // -> M (8 rows)
    const int m0 = blockIdx.y << 7;
    const int n0 = blockIdx.x << 7;

    const int row = tid >> 2;            // 0..63
    const int c4 = (tid & 3) << 2;       // 0,4,8,12

    const float* ap0 = A + (m0 + row) * DMODEL + c4;
    const float* ap1 = A + (m0 + row + 64) * DMODEL + c4;
    const float* bp0 = W + (n0 + row) * DMODEL + c4;
    const float* bp1 = W + (n0 + row + 64) * DMODEL + c4;

    unsigned long long acc[8][4];
#pragma unroll
    for (int i = 0; i < 8; i++)
#pragma unroll
        for (int p = 0; p < 4; p++) acc[i][p] = 0ull;

    for (int kt = 0; kt < DMODEL; kt += 16) {
        float4 va0 = *reinterpret_cast<const float4*>(ap0 + kt);
        float4 va1 = *reinterpret_cast<const float4*>(ap1 + kt);
        float4 vb0 = *reinterpret_cast<const float4*>(bp0 + kt);
        float4 vb1 = *reinterpret_cast<const float4*>(bp1 + kt);

        As[c4 + 0][row] = va0.x; As[c4 + 1][row] = va0.y;
        As[c4 + 2][row] = va0.z; As[c4 + 3][row] = va0.w;
        As[c4 + 0][row + 64] = va1.x; As[c4 + 1][row + 64] = va1.y;
        As[c4 + 2][row + 64] = va1.z; As[c4 + 3][row + 64] = va1.w;
        Bs[c4 + 0][row] = vb0.x; Bs[c4 + 1][row] = vb0.y;
        Bs[c4 + 2][row] = vb0.z; Bs[c4 + 3][row] = vb0.w;
        Bs[c4 + 0][row + 64] = vb1.x; Bs[c4 + 1][row + 64] = vb1.y;
        Bs[c4 + 2][row + 64] = vb1.z; Bs[c4 + 3][row + 64] = vb1.w;

        __syncthreads();

#pragma unroll
        for (int k = 0; k < 16; k++) {
            const float4 a0 = *reinterpret_cast<const float4*>(&As[k][ty << 3]);
            const float4 a1 = *reinterpret_cast<const float4*>(&As[k][(ty << 3) + 4]);
            const float4 b0 = *reinterpret_cast<const float4*>(&Bs[k][tx << 3]);
            const float4 b1 = *reinterpret_cast<const float4*>(&Bs[k][(tx << 3) + 4]);

            unsigned long long bp[4];
            bp[0] = f32x2_pack(b0.x, b0.y);
            bp[1] = f32x2_pack(b0.z, b0.w);
            bp[2] = f32x2_pack(b1.x, b1.y);
            bp[3] = f32x2_pack(b1.z, b1.w);

            float av[8] = {a0.x, a0.y, a0.z, a0.w, a1.x, a1.y, a1.z, a1.w};
#pragma unroll
            for (int i = 0; i < 8; i++) {
                unsigned long long ad = f32x2_dup(av[i]);
                acc[i][0] = f32x2_fma(ad, bp[0], acc[i][0]);
                acc[i][1] = f32x2_fma(ad, bp[1], acc[i][1]);
                acc[i][2] = f32x2_fma(ad, bp[2], acc[i][2]);
                acc[i][3] = f32x2_fma(ad, bp[3], acc[i][3]);
            }
        }
        __syncthreads();
    }

    // Epilogue: +bias, two float4 stores per row
    const int cbase = n0 + (tx << 3);
    float4 bvec0 = *reinterpret_cast<const float4*>(&bias[cbase]);
    float4 bvec1 = *reinterpret_cast<const float4*>(&bias[cbase + 4]);
#pragma unroll
    for (int i = 0; i < 8; i++) {
        const int r = m0 + (ty << 3) + i;
        float2 v0 = f32x2_unpack(acc[i][0]);
        float2 v1 = f32x2_unpack(acc[i][1]);
        float2 v2 = f32x2_unpack(acc[i][2]);
        float2 v3 = f32x2_unpack(acc[i][3]);
        float4 o0 = make_float4(v0.x + bvec0.x, v0.y + bvec0.y,
                                v1.x + bvec0.z, v1.y + bvec0.w);
        float4 o1 = make_float4(v2.x + bvec1.x, v2.y + bvec1.y,
                                v3.x + bvec1.z, v3.y + bvec1.w);
        *reinterpret_cast<float4*>(&C[r * DMODEL + cbase]) = o0;
        *reinterpret_cast<float4*>(&C[r * DMODEL + cbase + 4]) = o1;
    }
}

// ============================================================================
// compute_m: Mg[64,64] = (1/32) * Kg^T Vg ; Kg = Kflat[g*131072 ..].reshape(2048,64)
// One CTA per g (32 CTAs), 256 threads, 4x4 per thread, K-loop over 2048.
// ============================================================================
__global__ __launch_bounds__(256)
void compute_m(const float* __restrict__ Kb, const float* __restrict__ Vb,
               float* __restrict__ Mout) {
    const int g = blockIdx.x;
    __shared__ float Ks[32][64];
    __shared__ float Vs[32][64];

    const int tid = threadIdx.x;
    const int tx = tid & 15;   // d' (4 cols)
    const int ty = tid >> 4;   // d  (4 rows)

    const float* Kg = Kb + g * 131072;
    const float* Vg = Vb + g * 131072;

    unsigned long long acc[4][2];
#pragma unroll
    for (int i = 0; i < 4; i++) { acc[i][0] = 0ull; acc[i][1] = 0ull; }

    for (int t0 = 0; t0 < 2048; t0 += 32) {
#pragma unroll
        for (int s = 0; s < 2; s++) {
            int idx = tid + (s << 8);          // float4 index 0..511
            int tt = idx >> 4;
            int d4 = (idx & 15) << 2;
            *reinterpret_cast<float4*>(&Ks[tt][d4]) =
                *reinterpret_cast<const float4*>(&Kg[(t0 + tt) * 64 + d4]);
            *reinterpret_cast<float4*>(&Vs[tt][d4]) =
                *reinterpret_cast<const float4*>(&Vg[(t0 + tt) * 64 + d4]);
        }
        __syncthreads();
#pragma unroll 8
        for (int tt = 0; tt < 32; tt++) {
            float4 a = *reinterpret_cast<const float4*>(&Ks[tt][ty << 2]);
            float4 b = *reinterpret_cast<const float4*>(&Vs[tt][tx << 2]);
            unsigned long long bq0 = f32x2_pack(b.x, b.y);
            unsigned long long bq1 = f32x2_pack(b.z, b.w);
            float av[4] = {a.x, a.y, a.z, a.w};
#pragma unroll
            for (int i = 0; i < 4; i++) {
                unsigned long long ad = f32x2_dup(av[i]);
                acc[i][0] = f32x2_fma(ad, bq0, acc[i][0]);
                acc[i][1] = f32x2_fma(ad, bq1, acc[i][1]);
            }
        }
        __syncthreads();
    }

#pragma unroll
    for (int i = 0; i < 4; i++) {
        float2 v0 = f32x2_unpack(acc[i][0]);
        float2 v1 = f32x2_unpack(acc[i][1]);
        int d = (ty << 2) + i;
        int dp = tx << 2;
        float4 o = make_float4(v0.x * 0.03125f, v0.y * 0.03125f,
                               v1.x * 0.03125f, v1.y * 0.03125f);
        *reinterpret_cast<float4*>(&Mout[g * 4096 + d * 64 + dp]) = o;
    }
}

// ============================================================================
// apply_m: Out[r, j*64+d'] = sum_d Q[r, j*64+d] * M[g][d][d'],  g = r/128
// CTA per (j, g): [128,64] @ [64,64]. 256 threads, 8x4 per thread.
// ============================================================================
__global__ __launch_bounds__(256)
void apply_m(const float* __restrict__ Qb, const float* __restrict__ Mb,
             float* __restrict__ O) {
    const int j = blockIdx.x;   // 0..15
    const int g = blockIdx.y;   // 0..31

    __shared__ float Qs[64][128];  // [d][r]
    __shared__ float Ms[64][64];   // [d][d']

    const int tid = threadIdx.x;
    const int tx = tid & 15;    // d' (4 cols)
    const int ty = tid >> 4;    // r  (8 rows)

    // Load M[g]: 4096 floats = 1024 float4
#pragma unroll
    for (int s = 0; s < 4; s++) {
        int idx = tid + (s << 8);
        *reinterpret_cast<float4*>(&Ms[idx >> 4][(idx & 15) << 2]) =
            *reinterpret_cast<const float4*>(&Mb[g * 4096 + idx * 4]);
    }
    // Load Q tile transposed: rows g*128..+128, cols j*64..+64
#pragma unroll
    for (int s = 0; s < 8; s++) {
        int idx = tid + (s << 8);       // 0..2047
        int r = idx & 127;
        int d4 = (idx >> 7) << 2;
        float4 v = *reinterpret_cast<const float4*>(
            &Qb[(g * 128 + r) * DMODEL + (j << 6) + d4]);
        Qs[d4 + 0][r] = v.x; Qs[d4 + 1][r] = v.y;
        Qs[d4 + 2][r] = v.z; Qs[d4 + 3][r] = v.w;
    }
    __syncthreads();

    unsigned long long acc[8][2];
#pragma unroll
    for (int i = 0; i < 8; i++) { acc[i][0] = 0ull; acc[i][1] = 0ull; }

#pragma unroll 4
    for (int d = 0; d < 64; d++) {
        float4 a0 = *reinterpret_cast<const float4*>(&Qs[d][ty << 3]);
        float4 a1 = *reinterpret_cast<const float4*>(&Qs[d][(ty << 3) + 4]);
        float4 b = *reinterpret_cast<const float4*>(&Ms[d][tx << 2]);
        unsigned long long bq0 = f32x2_pack(b.x, b.y);
        unsigned long long bq1 = f32x2_pack(b.z, b.w);
        float av[8] = {a0.x, a0.y, a0.z, a0.w, a1.x, a1.y, a1.z, a1.w};
#pragma unroll
        for (int i = 0; i < 8; i++) {
            unsigned long long ad = f32x2_dup(av[i]);
            acc[i][0] = f32x2_fma(ad, bq0, acc[i][0]);
            acc[i][1] = f32x2_fma(ad, bq1, acc[i][1]);
        }
    }

#pragma unroll
    for (int i = 0; i < 8; i++) {
        int r = g * 128 + (ty << 3) + i;
        float2 v0 = f32x2_unpack(acc[i][0]);
        float2 v1 = f32x2_unpack(acc[i][1]);
        float4 o = make_float4(v0.x, v0.y, v1.x, v1.y);
        *reinterpret_cast<float4*>(&O[r * DMODEL + (j << 6) + (tx << 2)]) = o;
    }
}

// ============================================================================
extern "C" void kernel_launch(void* const* d_in, const int* in_sizes, int n_in,
                              void* d_out, int out_size) {
    const float* x   = (const float*)d_in[0];
    const float* y   = (const float*)d_in[1];
    const float* q_w = (const float*)d_in[2];
    const float* q_b = (const float*)d_in[3];
    const float* k_w = (const float*)d_in[4];
    const float* k_b = (const float*)d_in[5];
    const float* v_w = (const float*)d_in[6];
    const float* v_b = (const float*)d_in[7];
    const float* o_w = (const float*)d_in[8];
    const float* o_b = (const float*)d_in[9];
    float* out = (float*)d_out;

    float *Qp, *Kp, *Vp, *Op, *Mp;
    cudaGetSymbolAddress((void**)&Qp, g_Q);
    cudaGetSymbolAddress((void**)&Kp, g_K);
    cudaGetSymbolAddress((void**)&Vp, g_V);
    cudaGetSymbolAddress((void**)&Op, g_O);
    cudaGetSymbolAddress((void**)&Mp, g_M);

    dim3 ggrid(DMODEL / 128, MROWS / 128);  // (8, 32)

    gemm_nt_bias<<<ggrid, 256>>>(x, q_w, q_b, Qp);
    gemm_nt_bias<<<ggrid, 256>>>(x, k_w, k_b, Kp);
    gemm_nt_bias<<<ggrid, 256>>>(y, v_w, v_b, Vp);
    compute_m<<<32, 256>>>(Kp, Vp, Mp);
    apply_m<<<dim3(16, 32), 256>>>(Qp, Mp, Op);
    gemm_nt_bias<<<ggrid, 256>>>(Op, o_w, o_b, out);
}

// round 3
// speedup vs baseline: 2.0244x; 2.0244x over previous
#include <cuda_runtime.h>
#include <cuda_bf16.h>
#include <cstdint>

// ============================================================================
// Multihead_Attention (no-softmax => fully linear) on sm_100 (generic PTX).
//
//   split x,y,weights into bf16 hi/lo
//   Q = x @ q_w^T + q_b    (mma.sync bf16 3-term split GEMM, fp32 accum)
//   K = x @ k_w^T + k_b
//   V = y @ v_w^T + v_b
//   Mg[64,64] = (1/32) Kg^T Vg  per g in 0..31  (partial + reduce, fp32)
//   O rows(g) = Qg @ blockdiag(Mg)              (fp32 f32x2)
//   out = O @ o_w^T + o_b  (split GEMM)
// ============================================================================

#define MROWS 4096
#define DMODEL 1024

// fp32 intermediates
__device__ float g_Q[MROWS * DMODEL];
__device__ float g_K[MROWS * DMODEL];
__device__ float g_V[MROWS * DMODEL];
__device__ float g_O[MROWS * DMODEL];
__device__ float g_Mpart[8 * 32 * 64 * 64];
__device__ float g_M[32 * 64 * 64];

// bf16 split operands
__device__ __nv_bfloat16 g_xh[MROWS * DMODEL], g_xl[MROWS * DMODEL];
__device__ __nv_bfloat16 g_yh[MROWS * DMODEL], g_yl[MROWS * DMODEL];
__device__ __nv_bfloat16 g_oh[MROWS * DMODEL], g_ol[MROWS * DMODEL];
__device__ __nv_bfloat16 g_qwh[DMODEL * DMODEL], g_qwl[DMODEL * DMODEL];
__device__ __nv_bfloat16 g_kwh[DMODEL * DMODEL], g_kwl[DMODEL * DMODEL];
__device__ __nv_bfloat16 g_vwh[DMODEL * DMODEL], g_vwl[DMODEL * DMODEL];
__device__ __nv_bfloat16 g_owh[DMODEL * DMODEL], g_owl[DMODEL * DMODEL];

// ---------------- generic PTX helpers ---------------------------------------
__device__ __forceinline__ uint32_t smem_u32(const void* p) {
    uint32_t a;
    asm("{ .reg .u64 t; cvta.to.shared.u64 t, %1; cvt.u32.u64 %0, t; }"
        : "=r"(a) : "l"(p));
    return a;
}
__device__ __forceinline__ void cp16(uint32_t dst, const void* src) {
    asm volatile("cp.async.cg.shared.global [%0], [%1], 16;"
                 :: "r"(dst), "l"(src) : "memory");
}
__device__ __forceinline__ void ldsm4(uint32_t (&r)[4], uint32_t addr) {
    asm volatile("ldmatrix.sync.aligned.m8n8.x4.shared.b16 {%0,%1,%2,%3}, [%4];"
                 : "=r"(r[0]), "=r"(r[1]), "=r"(r[2]), "=r"(r[3]) : "r"(addr));
}
__device__ __forceinline__ void mma16816(float (&d)[4], const uint32_t (&a)[4],
                                         uint32_t b0, uint32_t b1) {
    asm volatile(
        "mma.sync.aligned.m16n8k16.row.col.f32.bf16.bf16.f32 "
        "{%0,%1,%2,%3}, {%4,%5,%6,%7}, {%8,%9}, {%0,%1,%2,%3};"
        : "+f"(d[0]), "+f"(d[1]), "+f"(d[2]), "+f"(d[3])
        : "r"(a[0]), "r"(a[1]), "r"(a[2]), "r"(a[3]), "r"(b0), "r"(b1));
}

// ---------------- f32x2 helpers (fp32 small kernels) -----------------------
__device__ __forceinline__ unsigned long long f32x2_dup(float x) {
    unsigned long long r; asm("mov.b64 %0, {%1, %1};" : "=l"(r) : "f"(x)); return r;
}
__device__ __forceinline__ unsigned long long f32x2_pack(float x, float y) {
    unsigned long long r; asm("mov.b64 %0, {%1, %2};" : "=l"(r) : "f"(x), "f"(y)); return r;
}
__device__ __forceinline__ unsigned long long f32x2_fma(unsigned long long a,
                                                        unsigned long long b,
                                                        unsigned long long c) {
    unsigned long long d;
    asm("fma.rn.f32x2 %0, %1, %2, %3;" : "=l"(d) : "l"(a), "l"(b), "l"(c));
    return d;
}
__device__ __forceinline__ float2 f32x2_unpack(unsigned long long v) {
    float2 r; asm("mov.b64 {%0, %1}, %2;" : "=f"(r.x), "=f"(r.y) : "l"(v)); return r;
}

// ============================================================================
// split: fp32 -> bf16 hi + bf16 lo(residual).  4 floats/thread.
// ============================================================================
__global__ __launch_bounds__(256)
void split_kernel(const float* __restrict__ src, __nv_bfloat16* __restrict__ hi,
                  __nv_bfloat16* __restrict__ lo, int n4) {
    int i = blockIdx.x * 256 + threadIdx.x;
    if (i >= n4) return;
    float4 v = reinterpret_cast<const float4*>(src)[i];
    __nv_bfloat16 h0 = __float2bfloat16(v.x), h1 = __float2bfloat16(v.y);
    __nv_bfloat16 h2 = __float2bfloat16(v.z), h3 = __float2bfloat16(v.w);
    __nv_bfloat16 l0 = __float2bfloat16(v.x - __bfloat162float(h0));
    __nv_bfloat16 l1 = __float2bfloat16(v.y - __bfloat162float(h1));
    __nv_bfloat16 l2 = __float2bfloat16(v.z - __bfloat162float(h2));
    __nv_bfloat16 l3 = __float2bfloat16(v.w - __bfloat162float(h3));
    __nv_bfloat162 hp0 = {h0, h1}, hp1 = {h2, h3};
    __nv_bfloat162 lp0 = {l0, l1}, lp1 = {l2, l3};
    uint2 hv = {*reinterpret_cast<uint32_t*>(&hp0), *reinterpret_cast<uint32_t*>(&hp1)};
    uint2 lv = {*reinterpret_cast<uint32_t*>(&lp0), *reinterpret_cast<uint32_t*>(&lp1)};
    reinterpret_cast<uint2*>(hi)[i] = hv;
    reinterpret_cast<uint2*>(lo)[i] = lv;
}

// ============================================================================
// Split GEMM via mma.sync: C[4096,1024] = A @ W^T + bias
// CTA tile 128(M) x 256(N), BK=32, 3 stages cp.async, 8 warps (warp 64x64).
// K-extended mainloop: 96 iters = 3 passes x 32  (AhWh, AlWh, AhWl).
// Grid (4, 32) = 128 CTAs (single wave).
// SMEM rows padded to 40 halves (80B) -> conflict-free ldmatrix phases.
// ============================================================================
#define GS_A_STAGE 10240              // 128*80
#define GS_B_BASE  30720              // 3*10240
#define GS_B_STAGE 20480              // 256*80
#define GS_TOTAL   (GS_B_BASE + 3 * GS_B_STAGE)   // 92160

__global__ __launch_bounds__(256, 1)
void gemm_mma(const __nv_bfloat16* __restrict__ Ah, const __nv_bfloat16* __restrict__ Al,
              const __nv_bfloat16* __restrict__ Wh, const __nv_bfloat16* __restrict__ Wl,
              const float* __restrict__ bias, float* __restrict__ C) {
    extern __shared__ __align__(128) char smem[];
    __shared__ float biasS[256];
    const uint32_t sbase = smem_u32(smem);
    const int tid = threadIdx.x;
    const int lane = tid & 31;
    const int wid = tid >> 5;
    const int n0 = blockIdx.x << 8;
    const int m0 = blockIdx.y << 7;

    biasS[tid] = bias[n0 + tid];

    auto load_stage = [&](int it, int s) {
        const int p = it >> 5;
        const int kcol = (it & 31) << 5;
        const __nv_bfloat16* ap = (p == 1) ? Al : Ah;
        const __nv_bfloat16* wp = (p == 2) ? Wl : Wh;
        const uint32_t sa = sbase + s * GS_A_STAGE;
        const uint32_t sb = sbase + GS_B_BASE + s * GS_B_STAGE;
#pragma unroll
        for (int u = 0; u < 2; u++) {
            int idx = tid + (u << 8);
            int r = idx >> 2, c = idx & 3;
            cp16(sa + r * 80 + c * 16, ap + (m0 + r) * DMODEL + kcol + c * 8);
        }
#pragma unroll
        for (int u = 0; u < 4; u++) {
            int idx = tid + (u << 8);
            int r = idx >> 2, c = idx & 3;
            cp16(sb + r * 80 + c * 16, wp + (n0 + r) * DMODEL + kcol + c * 8);
        }
    };

    load_stage(0, 0);
    asm volatile("cp.async.commit_group;" ::: "memory");
    load_stage(1, 1);
    asm volatile("cp.async.commit_group;" ::: "memory");

    float d[4][8][4];
#pragma unroll
    for (int mf = 0; mf < 4; mf++)
#pragma unroll
        for (int nf = 0; nf < 8; nf++)
#pragma unroll
            for (int q = 0; q < 4; q++) d[mf][nf][q] = 0.f;

    const int warpM = (wid >> 2) << 6;   // 0 or 64
    const int warpN = (wid & 3) << 6;    // 0,64,128,192
    // ldmatrix lane address components (bytes)
    const uint32_t aLane = (warpM + (lane & 15)) * 80 + (lane >> 4) * 16;
    const uint32_t bLane = (warpN + ((lane >> 4) & 1) * 8 + (lane & 7)) * 80 +
                           ((lane >> 3) & 1) * 16;

    for (int it = 0; it < 96; ++it) {
        const int buf = it % 3;
        if (it < 94)
            asm volatile("cp.async.wait_group 1;" ::: "memory");
        else
            asm volatile("cp.async.wait_group 0;" ::: "memory");
        __syncthreads();
        if (it + 2 < 96) {
            load_stage(it + 2, (it + 2) % 3);
            asm volatile("cp.async.commit_group;" ::: "memory");
        }
        const uint32_t sa = sbase + buf * GS_A_STAGE + aLane;
        const uint32_t sb = sbase + GS_B_BASE + buf * GS_B_STAGE + bLane;
#pragma unroll
        for (int kc = 0; kc < 2; kc++) {
            uint32_t a[4][4], b[4][4];
#pragma unroll
            for (int mf = 0; mf < 4; mf++) ldsm4(a[mf], sa + mf * 1280 + kc * 32);
#pragma unroll
            for (int nf2 = 0; nf2 < 4; nf2++) ldsm4(b[nf2], sb + nf2 * 1280 + kc * 32);
#pragma unroll
            for (int mf = 0; mf < 4; mf++)
#pragma unroll
                for (int nf = 0; nf < 8; nf++)
                    mma16816(d[mf][nf], a[mf], b[nf >> 1][(nf & 1) * 2],
                             b[nf >> 1][(nf & 1) * 2 + 1]);
        }
    }

    // Epilogue: bias + store fp32
    const int rsub = lane >> 2;
    const int csub = (lane & 3) * 2;
#pragma unroll
    for (int mf = 0; mf < 4; mf++) {
#pragma unroll
        for (int nf = 0; nf < 8; nf++) {
            const int row = m0 + warpM + mf * 16 + rsub;
            const int colL = warpN + nf * 8 + csub;      // local col in [0,256)
            const float b0 = biasS[colL], b1 = biasS[colL + 1];
            float2 v0 = make_float2(d[mf][nf][0] + b0, d[mf][nf][1] + b1);
            float2 v1 = make_float2(d[mf][nf][2] + b0, d[mf][nf][3] + b1);
            *reinterpret_cast<float2*>(&C[(size_t)row * DMODEL + n0 + colL]) = v0;
            *reinterpret_cast<float2*>(&C[(size_t)(row + 8) * DMODEL + n0 + colL]) = v1;
        }
    }
}

// ============================================================================
// compute_m_partial: Mpart[s][g] = sum over t in [s*256,(s+1)*256) Kg[t]^T Vg[t]
// grid (8, 32), 256 threads, 4x4 per thread.
// ============================================================================
__global__ __launch_bounds__(256)
void compute_m_partial(const float* __restrict__ Kb, const float* __restrict__ Vb,
                       float* __restrict__ Mpart) {
    const int s = blockIdx.x;
    const int g = blockIdx.y;
    __shared__ float Ks[32][64];
    __shared__ float Vs[32][64];

    const int tid = threadIdx.x;
    const int tx = tid & 15;
    const int ty = tid >> 4;

    const float* Kg = Kb + g * 131072 + s * 256 * 64;
    const float* Vg = Vb + g * 131072 + s * 256 * 64;

    unsigned long long acc[4][2];
#pragma unroll
    for (int i = 0; i < 4; i++) { acc[i][0] = 0ull; acc[i][1] = 0ull; }

    for (int t0 = 0; t0 < 256; t0 += 32) {
#pragma unroll
        for (int sr = 0; sr < 2; sr++) {
            int idx = tid + (sr << 8);
            int tt = idx >> 4;
            int d4 = (idx & 15) << 2;
            *reinterpret_cast<float4*>(&Ks[tt][d4]) =
                *reinterpret_cast<const float4*>(&Kg[(t0 + tt) * 64 + d4]);
            *reinterpret_cast<float4*>(&Vs[tt][d4]) =
                *reinterpret_cast<const float4*>(&Vg[(t0 + tt) * 64 + d4]);
        }
        __syncthreads();
#pragma unroll 8
        for (int tt = 0; tt < 32; tt++) {
            float4 a = *reinterpret_cast<const float4*>(&Ks[tt][ty << 2]);
            float4 b = *reinterpret_cast<const float4*>(&Vs[tt][tx << 2]);
            unsigned long long bq0 = f32x2_pack(b.x, b.y);
            unsigned long long bq1 = f32x2_pack(b.z, b.w);
            float av[4] = {a.x, a.y, a.z, a.w};
#pragma unroll
            for (int i = 0; i < 4; i++) {
                unsigned long long ad = f32x2_dup(av[i]);
                acc[i][0] = f32x2_fma(ad, bq0, acc[i][0]);
                acc[i][1] = f32x2_fma(ad, bq1, acc[i][1]);
            }
        }
        __syncthreads();
    }

#pragma unroll
    for (int i = 0; i < 4; i++) {
        float2 v0 = f32x2_unpack(acc[i][0]);
        float2 v1 = f32x2_unpack(acc[i][1]);
        int d = (ty << 2) + i;
        int dp = tx << 2;
        float4 o = make_float4(v0.x, v0.y, v1.x, v1.y);
        *reinterpret_cast<float4*>(&Mpart[(s * 32 + g) * 4096 + d * 64 + dp]) = o;
    }
}

__global__ __launch_bounds__(256)
void reduce_m(const float* __restrict__ Mpart, float* __restrict__ M) {
    int i = blockIdx.x * 256 + threadIdx.x;  // 131072 elems
    float acc = 0.f;
#pragma unroll
    for (int s = 0; s < 8; s++) acc += Mpart[s * 131072 + i];
    M[i] = acc * 0.03125f;
}

// ============================================================================
// apply_m: O[r, j*64+d'] = sum_d Q[r, j*64+d] * M[g][d][d'],  g = r/128
// ============================================================================
__global__ __launch_bounds__(256)
void apply_m(const float* __restrict__ Qb, const float* __restrict__ Mb,
             float* __restrict__ O) {
    const int j = blockIdx.x;
    const int g = blockIdx.y;

    __shared__ float Qs[64][128];
    __shared__ float Ms[64][64];

    const int tid = threadIdx.x;
    const int tx = tid & 15;
    const int ty = tid >> 4;

#pragma unroll
    for (int s = 0; s < 4; s++) {
        int idx = tid + (s << 8);
        *reinterpret_cast<float4*>(&Ms[idx >> 4][(idx & 15) << 2]) =
            *reinterpret_cast<const float4*>(&Mb[g * 4096 + idx * 4]);
    }
#pragma unroll
    for (int s = 0; s < 8; s++) {
        int idx = tid + (s << 8);
        int r = idx & 127;
        int d4 = (idx >> 7) << 2;
        float4 v = *reinterpret_cast<const float4*>(
            &Qb[(g * 128 + r) * DMODEL + (j << 6) + d4]);
        Qs[d4 + 0][r] = v.x; Qs[d4 + 1][r] = v.y;
        Qs[d4 + 2][r] = v.z; Qs[d4 + 3][r] = v.w;
    }
    __syncthreads();

    unsigned long long acc[8][2];
#pragma unroll
    for (int i = 0; i < 8; i++) { acc[i][0] = 0ull; acc[i][1] = 0ull; }

#pragma unroll 4
    for (int d = 0; d < 64; d++) {
        float4 a0 = *reinterpret_cast<const float4*>(&Qs[d][ty << 3]);
        float4 a1 = *reinterpret_cast<const float4*>(&Qs[d][(ty << 3) + 4]);
        float4 b = *reinterpret_cast<const float4*>(&Ms[d][tx << 2]);
        unsigned long long bq0 = f32x2_pack(b.x, b.y);
        unsigned long long bq1 = f32x2_pack(b.z, b.w);
        float av[8] = {a0.x, a0.y, a0.z, a0.w, a1.x, a1.y, a1.z, a1.w};
#pragma unroll
        for (int i = 0; i < 8; i++) {
            unsigned long long ad = f32x2_dup(av[i]);
            acc[i][0] = f32x2_fma(ad, bq0, acc[i][0]);
            acc[i][1] = f32x2_fma(ad, bq1, acc[i][1]);
        }
    }

#pragma unroll
    for (int i = 0; i < 8; i++) {
        int r = g * 128 + (ty << 3) + i;
        float2 v0 = f32x2_unpack(acc[i][0]);
        float2 v1 = f32x2_unpack(acc[i][1]);
        float4 o = make_float4(v0.x, v0.y, v1.x, v1.y);
        *reinterpret_cast<float4*>(&O[r * DMODEL + (j << 6) + (tx << 2)]) = o;
    }
}

// ============================================================================
extern "C" void kernel_launch(void* const* d_in, const int* in_sizes, int n_in,
                              void* d_out, int out_size) {
    const float* x   = (const float*)d_in[0];
    const float* y   = (const float*)d_in[1];
    const float* q_w = (const float*)d_in[2];
    const float* q_b = (const float*)d_in[3];
    const float* k_w = (const float*)d_in[4];
    const float* k_b = (const float*)d_in[5];
    const float* v_w = (const float*)d_in[6];
    const float* v_b = (const float*)d_in[7];
    const float* o_w = (const float*)d_in[8];
    const float* o_b = (const float*)d_in[9];
    float* out = (float*)d_out;

    float *Qp, *Kp, *Vp, *Op, *Mpp, *Mp;
    cudaGetSymbolAddress((void**)&Qp, g_Q);
    cudaGetSymbolAddress((void**)&Kp, g_K);
    cudaGetSymbolAddress((void**)&Vp, g_V);
    cudaGetSymbolAddress((void**)&Op, g_O);
    cudaGetSymbolAddress((void**)&Mpp, g_Mpart);
    cudaGetSymbolAddress((void**)&Mp, g_M);

    __nv_bfloat16 *xh, *xl, *yh, *yl, *oh, *ol;
    __nv_bfloat16 *qwh, *qwl, *kwh, *kwl, *vwh, *vwl, *owh, *owl;
    cudaGetSymbolAddress((void**)&xh, g_xh);  cudaGetSymbolAddress((void**)&xl, g_xl);
    cudaGetSymbolAddress((void**)&yh, g_yh);  cudaGetSymbolAddress((void**)&yl, g_yl);
    cudaGetSymbolAddress((void**)&oh, g_oh);  cudaGetSymbolAddress((void**)&ol, g_ol);
    cudaGetSymbolAddress((void**)&qwh, g_qwh); cudaGetSymbolAddress((void**)&qwl, g_qwl);
    cudaGetSymbolAddress((void**)&kwh, g_kwh); cudaGetSymbolAddress((void**)&kwl, g_kwl);
    cudaGetSymbolAddress((void**)&vwh, g_vwh); cudaGetSymbolAddress((void**)&vwl, g_vwl);
    cudaGetSymbolAddress((void**)&owh, g_owh); cudaGetSymbolAddress((void**)&owl, g_owl);

    cudaFuncSetAttribute(gemm_mma, cudaFuncAttributeMaxDynamicSharedMemorySize,
                         GS_TOTAL);

    const int n4_act = MROWS * DMODEL / 4;    // 1048576
    const int n4_w = DMODEL * DMODEL / 4;     // 262144

    split_kernel<<<n4_act / 256, 256>>>(x, xh, xl, n4_act);
    split_kernel<<<n4_act / 256, 256>>>(y, yh, yl, n4_act);
    split_kernel<<<n4_w / 256, 256>>>(q_w, qwh, qwl, n4_w);
    split_kernel<<<n4_w / 256, 256>>>(k_w, kwh, kwl, n4_w);
    split_kernel<<<n4_w / 256, 256>>>(v_w, vwh, vwl, n4_w);
    split_kernel<<<n4_w / 256, 256>>>(o_w, owh, owl, n4_w);

    dim3 tgrid(DMODEL / 256, MROWS / 128);  // (4, 32)
    gemm_mma<<<tgrid, 256, GS_TOTAL>>>(xh, xl, qwh, qwl, q_b, Qp);
    gemm_mma<<<tgrid, 256, GS_TOTAL>>>(xh, xl, kwh, kwl, k_b, Kp);
    gemm_mma<<<tgrid, 256, GS_TOTAL>>>(yh, yl, vwh, vwl, v_b, Vp);

    compute_m_partial<<<dim3(8, 32), 256>>>(Kp, Vp, Mpp);
    reduce_m<<<512, 256>>>(Mpp, Mp);
    apply_m<<<dim3(16, 32), 256>>>(Qp, Mp, Op);

    split_kernel<<<n4_act / 256, 256>>>(Op, oh, ol, n4_act);
    gemm_mma<<<tgrid, 256, GS_TOTAL>>>(oh, ol, owh, owl, o_b, out);
}

// round 4
// speedup vs baseline: 2.3105x; 1.1413x over previous
#include <cuda_runtime.h>
#include <cuda_bf16.h>
#include <cstdint>

// ============================================================================
// Multihead_Attention (no-softmax => fully linear) on sm_100 (generic PTX).
//   split x,y,weights into bf16 hi/lo (fused launches)
//   Q,K,V = one merged 3-GEMM launch (mma.sync bf16 3-term split, fp32 accum)
//   Mg[64,64] = (1/32) Kg^T Vg  (partial + reduce, fp32)
//   O rows(g) = Qg @ blockdiag(Mg)  -> emitted directly as bf16 hi/lo
//   out = O @ o_w^T + o_b  (split GEMM)
// ============================================================================

#define MROWS 4096
#define DMODEL 1024

// fp32 intermediates
__device__ float g_Q[MROWS * DMODEL];
__device__ float g_K[MROWS * DMODEL];
__device__ float g_V[MROWS * DMODEL];
__device__ float g_Mpart[8 * 32 * 64 * 64];
__device__ float g_M[32 * 64 * 64];

// bf16 split operands
__device__ __nv_bfloat16 g_xh[MROWS * DMODEL], g_xl[MROWS * DMODEL];
__device__ __nv_bfloat16 g_yh[MROWS * DMODEL], g_yl[MROWS * DMODEL];
__device__ __nv_bfloat16 g_oh[MROWS * DMODEL], g_ol[MROWS * DMODEL];
__device__ __nv_bfloat16 g_qwh[DMODEL * DMODEL], g_qwl[DMODEL * DMODEL];
__device__ __nv_bfloat16 g_kwh[DMODEL * DMODEL], g_kwl[DMODEL * DMODEL];
__device__ __nv_bfloat16 g_vwh[DMODEL * DMODEL], g_vwl[DMODEL * DMODEL];
__device__ __nv_bfloat16 g_owh[DMODEL * DMODEL], g_owl[DMODEL * DMODEL];

// ---------------- generic PTX helpers ---------------------------------------
__device__ __forceinline__ uint32_t smem_u32(const void* p) {
    uint32_t a;
    asm("{ .reg .u64 t; cvta.to.shared.u64 t, %1; cvt.u32.u64 %0, t; }"
        : "=r"(a) : "l"(p));
    return a;
}
__device__ __forceinline__ void cp16(uint32_t dst, const void* src) {
    asm volatile("cp.async.cg.shared.global [%0], [%1], 16;"
                 :: "r"(dst), "l"(src) : "memory");
}
__device__ __forceinline__ void ldsm4(uint32_t (&r)[4], uint32_t addr) {
    asm volatile("ldmatrix.sync.aligned.m8n8.x4.shared.b16 {%0,%1,%2,%3}, [%4];"
                 : "=r"(r[0]), "=r"(r[1]), "=r"(r[2]), "=r"(r[3]) : "r"(addr));
}
__device__ __forceinline__ void mma16816(float (&d)[4], const uint32_t (&a)[4],
                                         uint32_t b0, uint32_t b1) {
    asm volatile(
        "mma.sync.aligned.m16n8k16.row.col.f32.bf16.bf16.f32 "
        "{%0,%1,%2,%3}, {%4,%5,%6,%7}, {%8,%9}, {%0,%1,%2,%3};"
        : "+f"(d[0]), "+f"(d[1]), "+f"(d[2]), "+f"(d[3])
        : "r"(a[0]), "r"(a[1]), "r"(a[2]), "r"(a[3]), "r"(b0), "r"(b1));
}

// ---------------- f32x2 helpers ---------------------------------------------
__device__ __forceinline__ unsigned long long f32x2_dup(float x) {
    unsigned long long r; asm("mov.b64 %0, {%1, %1};" : "=l"(r) : "f"(x)); return r;
}
__device__ __forceinline__ unsigned long long f32x2_pack(float x, float y) {
    unsigned long long r; asm("mov.b64 %0, {%1, %2};" : "=l"(r) : "f"(x), "f"(y)); return r;
}
__device__ __forceinline__ unsigned long long f32x2_fma(unsigned long long a,
                                                        unsigned long long b,
                                                        unsigned long long c) {
    unsigned long long d;
    asm("fma.rn.f32x2 %0, %1, %2, %3;" : "=l"(d) : "l"(a), "l"(b), "l"(c));
    return d;
}
__device__ __forceinline__ float2 f32x2_unpack(unsigned long long v) {
    float2 r; asm("mov.b64 {%0, %1}, %2;" : "=f"(r.x), "=f"(r.y) : "l"(v)); return r;
}

// pack 4 fp32 -> bf16 hi uint2 + lo uint2
__device__ __forceinline__ void split4(float4 v, uint2& hv, uint2& lv) {
    __nv_bfloat16 h0 = __float2bfloat16(v.x), h1 = __float2bfloat16(v.y);
    __nv_bfloat16 h2 = __float2bfloat16(v.z), h3 = __float2bfloat16(v.w);
    __nv_bfloat16 l0 = __float2bfloat16(v.x - __bfloat162float(h0));
    __nv_bfloat16 l1 = __float2bfloat16(v.y - __bfloat162float(h1));
    __nv_bfloat16 l2 = __float2bfloat16(v.z - __bfloat162float(h2));
    __nv_bfloat16 l3 = __float2bfloat16(v.w - __bfloat162float(h3));
    __nv_bfloat162 hp0 = {h0, h1}, hp1 = {h2, h3};
    __nv_bfloat162 lp0 = {l0, l1}, lp1 = {l2, l3};
    hv.x = *reinterpret_cast<uint32_t*>(&hp0); hv.y = *reinterpret_cast<uint32_t*>(&hp1);
    lv.x = *reinterpret_cast<uint32_t*>(&lp0); lv.y = *reinterpret_cast<uint32_t*>(&lp1);
}

// ============================================================================
// fused activation split: z=0 -> x, z=1 -> y
// ============================================================================
__global__ __launch_bounds__(256)
void split_act(const float* __restrict__ x, const float* __restrict__ y,
               __nv_bfloat16* __restrict__ xh, __nv_bfloat16* __restrict__ xl,
               __nv_bfloat16* __restrict__ yh, __nv_bfloat16* __restrict__ yl) {
    const float* src = blockIdx.y ? y : x;
    __nv_bfloat16* hi = blockIdx.y ? yh : xh;
    __nv_bfloat16* lo = blockIdx.y ? yl : xl;
    int i = blockIdx.x * 256 + threadIdx.x;
    float4 v = reinterpret_cast<const float4*>(src)[i];
    uint2 hv, lv;
    split4(v, hv, lv);
    reinterpret_cast<uint2*>(hi)[i] = hv;
    reinterpret_cast<uint2*>(lo)[i] = lv;
}

// fused weight split: z selects among 4 weight matrices
__global__ __launch_bounds__(256)
void split_w(const float* __restrict__ w0, const float* __restrict__ w1,
             const float* __restrict__ w2, const float* __restrict__ w3,
             __nv_bfloat16* __restrict__ h0, __nv_bfloat16* __restrict__ l0,
             __nv_bfloat16* __restrict__ h1, __nv_bfloat16* __restrict__ l1,
             __nv_bfloat16* __restrict__ h2, __nv_bfloat16* __restrict__ l2,
             __nv_bfloat16* __restrict__ h3, __nv_bfloat16* __restrict__ l3) {
    const float* srcs[4] = {w0, w1, w2, w3};
    __nv_bfloat16* his[4] = {h0, h1, h2, h3};
    __nv_bfloat16* los[4] = {l0, l1, l2, l3};
    const float* src = srcs[blockIdx.y];
    __nv_bfloat16* hi = his[blockIdx.y];
    __nv_bfloat16* lo = los[blockIdx.y];
    int i = blockIdx.x * 256 + threadIdx.x;
    float4 v = reinterpret_cast<const float4*>(src)[i];
    uint2 hv, lv;
    split4(v, hv, lv);
    reinterpret_cast<uint2*>(hi)[i] = hv;
    reinterpret_cast<uint2*>(lo)[i] = lv;
}

// ============================================================================
// Split GEMM core via mma.sync: C[4096,1024] = A @ W^T + bias
// CTA tile 128(M) x 256(N), BK=64, 3 stages cp.async, 8 warps (warp 64x64).
// K-extended mainloop: 48 iters = 3 passes x 16  (AhWh, AlWh, AhWl).
// SMEM rows padded to 72 halves (144B) -> conflict-free (9r mod 8 distinct).
// ============================================================================
#define GS_A_STAGE 18432              // 128*144
#define GS_B_BASE  55296              // 3*18432
#define GS_B_STAGE 36864              // 256*144
#define GS_TOTAL   (GS_B_BASE + 3 * GS_B_STAGE)   // 165888

__device__ __forceinline__
void gemm_core(const __nv_bfloat16* __restrict__ Ah, const __nv_bfloat16* __restrict__ Al,
               const __nv_bfloat16* __restrict__ Wh, const __nv_bfloat16* __restrict__ Wl,
               const float* __restrict__ bias, float* __restrict__ C,
               char* smem, float* biasS, int m0, int n0) {
    const uint32_t sbase = smem_u32(smem);
    const int tid = threadIdx.x;
    const int lane = tid & 31;
    const int wid = tid >> 5;

    biasS[tid] = bias[n0 + tid];

    auto load_stage = [&](int it, int s) {
        const int p = it >> 4;                 // pass 0/1/2
        const int kcol = (it & 15) << 6;       // K offset (64 per stage)
        const __nv_bfloat16* ap = (p == 1) ? Al : Ah;
        const __nv_bfloat16* wp = (p == 2) ? Wl : Wh;
        const uint32_t sa = sbase + s * GS_A_STAGE;
        const uint32_t sb = sbase + GS_B_BASE + s * GS_B_STAGE;
#pragma unroll
        for (int u = 0; u < 4; u++) {
            int idx = tid + (u << 8);
            int r = idx >> 3, c = idx & 7;
            cp16(sa + r * 144 + c * 16, ap + (m0 + r) * DMODEL + kcol + c * 8);
        }
#pragma unroll
        for (int u = 0; u < 8; u++) {
            int idx = tid + (u << 8);
            int r = idx >> 3, c = idx & 7;
            cp16(sb + r * 144 + c * 16, wp + (n0 + r) * DMODEL + kcol + c * 8);
        }
    };

    load_stage(0, 0);
    asm volatile("cp.async.commit_group;" ::: "memory");
    load_stage(1, 1);
    asm volatile("cp.async.commit_group;" ::: "memory");

    float d[4][8][4];
#pragma unroll
    for (int mf = 0; mf < 4; mf++)
#pragma unroll
        for (int nf = 0; nf < 8; nf++)
#pragma unroll
            for (int q = 0; q < 4; q++) d[mf][nf][q] = 0.f;

    const int warpM = (wid >> 2) << 6;   // 0 or 64
    const int warpN = (wid & 3) << 6;    // 0,64,128,192
    const uint32_t aLane = (warpM + (lane & 15)) * 144 + (lane >> 4) * 16;
    const uint32_t bLane = (warpN + ((lane >> 4) & 1) * 8 + (lane & 7)) * 144 +
                           ((lane >> 3) & 1) * 16;

    for (int it = 0; it < 48; ++it) {
        const int buf = it % 3;
        if (it < 46)
            asm volatile("cp.async.wait_group 1;" ::: "memory");
        else
            asm volatile("cp.async.wait_group 0;" ::: "memory");
        __syncthreads();
        if (it + 2 < 48) {
            load_stage(it + 2, (it + 2) % 3);
            asm volatile("cp.async.commit_group;" ::: "memory");
        }
        const uint32_t sa = sbase + buf * GS_A_STAGE + aLane;
        const uint32_t sb = sbase + GS_B_BASE + buf * GS_B_STAGE + bLane;
#pragma unroll
        for (int kc = 0; kc < 4; kc++) {
            uint32_t a[4][4], b[4][4];
#pragma unroll
            for (int mf = 0; mf < 4; mf++) ldsm4(a[mf], sa + mf * 2304 + kc * 32);
#pragma unroll
            for (int nf2 = 0; nf2 < 4; nf2++) ldsm4(b[nf2], sb + nf2 * 2304 + kc * 32);
#pragma unroll
            for (int mf = 0; mf < 4; mf++)
#pragma unroll
                for (int nf = 0; nf < 8; nf++)
                    mma16816(d[mf][nf], a[mf], b[nf >> 1][(nf & 1) * 2],
                             b[nf >> 1][(nf & 1) * 2 + 1]);
        }
    }

    const int rsub = lane >> 2;
    const int csub = (lane & 3) * 2;
#pragma unroll
    for (int mf = 0; mf < 4; mf++) {
#pragma unroll
        for (int nf = 0; nf < 8; nf++) {
            const int row = m0 + warpM + mf * 16 + rsub;
            const int colL = warpN + nf * 8 + csub;
            const float b0 = biasS[colL], b1 = biasS[colL + 1];
            float2 v0 = make_float2(d[mf][nf][0] + b0, d[mf][nf][1] + b1);
            float2 v1 = make_float2(d[mf][nf][2] + b0, d[mf][nf][3] + b1);
            *reinterpret_cast<float2*>(&C[(size_t)row * DMODEL + n0 + colL]) = v0;
            *reinterpret_cast<float2*>(&C[(size_t)(row + 8) * DMODEL + n0 + colL]) = v1;
        }
    }
}

// merged Q/K/V projections: blockIdx.z selects the GEMM
__global__ __launch_bounds__(256, 1)
void gemm_qkv(const __nv_bfloat16* __restrict__ xh, const __nv_bfloat16* __restrict__ xl,
              const __nv_bfloat16* __restrict__ yh, const __nv_bfloat16* __restrict__ yl,
              const __nv_bfloat16* __restrict__ qwh, const __nv_bfloat16* __restrict__ qwl,
              const __nv_bfloat16* __restrict__ kwh, const __nv_bfloat16* __restrict__ kwl,
              const __nv_bfloat16* __restrict__ vwh, const __nv_bfloat16* __restrict__ vwl,
              const float* __restrict__ q_b, const float* __restrict__ k_b,
              const float* __restrict__ v_b,
              float* __restrict__ Q, float* __restrict__ K, float* __restrict__ V) {
    extern __shared__ __align__(128) char smem[];
    __shared__ float biasS[256];
    const int z = blockIdx.z;
    const __nv_bfloat16* Ah = (z == 2) ? yh : xh;
    const __nv_bfloat16* Al = (z == 2) ? yl : xl;
    const __nv_bfloat16* Wh = (z == 0) ? qwh : (z == 1) ? kwh : vwh;
    const __nv_bfloat16* Wl = (z == 0) ? qwl : (z == 1) ? kwl : vwl;
    const float* bias = (z == 0) ? q_b : (z == 1) ? k_b : v_b;
    float* C = (z == 0) ? Q : (z == 1) ? K : V;
    gemm_core(Ah, Al, Wh, Wl, bias, C, smem, biasS,
              blockIdx.y << 7, blockIdx.x << 8);
}

__global__ __launch_bounds__(256, 1)
void gemm_single(const __nv_bfloat16* __restrict__ Ah, const __nv_bfloat16* __restrict__ Al,
                 const __nv_bfloat16* __restrict__ Wh, const __nv_bfloat16* __restrict__ Wl,
                 const float* __restrict__ bias, float* __restrict__ C) {
    extern __shared__ __align__(128) char smem[];
    __shared__ float biasS[256];
    gemm_core(Ah, Al, Wh, Wl, bias, C, smem, biasS,
              blockIdx.y << 7, blockIdx.x << 8);
}

// ============================================================================
// compute_m_partial: Mpart[s][g] = sum over t in [s*256,(s+1)*256) Kg[t]^T Vg[t]
// ============================================================================
__global__ __launch_bounds__(256)
void compute_m_partial(const float* __restrict__ Kb, const float* __restrict__ Vb,
                       float* __restrict__ Mpart) {
    const int s = blockIdx.x;
    const int g = blockIdx.y;
    __shared__ float Ks[32][64];
    __shared__ float Vs[32][64];

    const int tid = threadIdx.x;
    const int tx = tid & 15;
    const int ty = tid >> 4;

    const float* Kg = Kb + g * 131072 + s * 256 * 64;
    const float* Vg = Vb + g * 131072 + s * 256 * 64;

    unsigned long long acc[4][2];
#pragma unroll
    for (int i = 0; i < 4; i++) { acc[i][0] = 0ull; acc[i][1] = 0ull; }

    for (int t0 = 0; t0 < 256; t0 += 32) {
#pragma unroll
        for (int sr = 0; sr < 2; sr++) {
            int idx = tid + (sr << 8);
            int tt = idx >> 4;
            int d4 = (idx & 15) << 2;
            *reinterpret_cast<float4*>(&Ks[tt][d4]) =
                *reinterpret_cast<const float4*>(&Kg[(t0 + tt) * 64 + d4]);
            *reinterpret_cast<float4*>(&Vs[tt][d4]) =
                *reinterpret_cast<const float4*>(&Vg[(t0 + tt) * 64 + d4]);
        }
        __syncthreads();
#pragma unroll 8
        for (int tt = 0; tt < 32; tt++) {
            float4 a = *reinterpret_cast<const float4*>(&Ks[tt][ty << 2]);
            float4 b = *reinterpret_cast<const float4*>(&Vs[tt][tx << 2]);
            unsigned long long bq0 = f32x2_pack(b.x, b.y);
            unsigned long long bq1 = f32x2_pack(b.z, b.w);
            float av[4] = {a.x, a.y, a.z, a.w};
#pragma unroll
            for (int i = 0; i < 4; i++) {
                unsigned long long ad = f32x2_dup(av[i]);
                acc[i][0] = f32x2_fma(ad, bq0, acc[i][0]);
                acc[i][1] = f32x2_fma(ad, bq1, acc[i][1]);
            }
        }
        __syncthreads();
    }

#pragma unroll
    for (int i = 0; i < 4; i++) {
        float2 v0 = f32x2_unpack(acc[i][0]);
        float2 v1 = f32x2_unpack(acc[i][1]);
        int d = (ty << 2) + i;
        int dp = tx << 2;
        float4 o = make_float4(v0.x, v0.y, v1.x, v1.y);
        *reinterpret_cast<float4*>(&Mpart[(s * 32 + g) * 4096 + d * 64 + dp]) = o;
    }
}

__global__ __launch_bounds__(256)
void reduce_m(const float* __restrict__ Mpart, float* __restrict__ M) {
    int i = blockIdx.x * 256 + threadIdx.x;
    float acc = 0.f;
#pragma unroll
    for (int s = 0; s < 8; s++) acc += Mpart[s * 131072 + i];
    M[i] = acc * 0.03125f;
}

// ============================================================================
// apply_m: O[r, j*64+d'] = sum_d Q[r, j*64+d] * M[g][d][d'],  g = r/128
// Emits bf16 hi/lo directly (feeds output-projection GEMM).
// ============================================================================
__global__ __launch_bounds__(256)
void apply_m(const float* __restrict__ Qb, const float* __restrict__ Mb,
             __nv_bfloat16* __restrict__ Oh, __nv_bfloat16* __restrict__ Ol) {
    const int j = blockIdx.x;
    const int g = blockIdx.y;

    __shared__ float Qs[64][128];
    __shared__ float Ms[64][64];

    const int tid = threadIdx.x;
    const int tx = tid & 15;
    const int ty = tid >> 4;

#pragma unroll
    for (int s = 0; s < 4; s++) {
        int idx = tid + (s << 8);
        *reinterpret_cast<float4*>(&Ms[idx >> 4][(idx & 15) << 2]) =
            *reinterpret_cast<const float4*>(&Mb[g * 4096 + idx * 4]);
    }
#pragma unroll
    for (int s = 0; s < 8; s++) {
        int idx = tid + (s << 8);
        int r = idx & 127;
        int d4 = (idx >> 7) << 2;
        float4 v = *reinterpret_cast<const float4*>(
            &Qb[(g * 128 + r) * DMODEL + (j << 6) + d4]);
        Qs[d4 + 0][r] = v.x; Qs[d4 + 1][r] = v.y;
        Qs[d4 + 2][r] = v.z; Qs[d4 + 3][r] = v.w;
    }
    __syncthreads();

    unsigned long long acc[8][2];
#pragma unroll
    for (int i = 0; i < 8; i++) { acc[i][0] = 0ull; acc[i][1] = 0ull; }

#pragma unroll 4
    for (int d = 0; d < 64; d++) {
        float4 a0 = *reinterpret_cast<const float4*>(&Qs[d][ty << 3]);
        float4 a1 = *reinterpret_cast<const float4*>(&Qs[d][(ty << 3) + 4]);
        float4 b = *reinterpret_cast<const float4*>(&Ms[d][tx << 2]);
        unsigned long long bq0 = f32x2_pack(b.x, b.y);
        unsigned long long bq1 = f32x2_pack(b.z, b.w);
        float av[8] = {a0.x, a0.y, a0.z, a0.w, a1.x, a1.y, a1.z, a1.w};
#pragma unroll
        for (int i = 0; i < 8; i++) {
            unsigned long long ad = f32x2_dup(av[i]);
            acc[i][0] = f32x2_fma(ad, bq0, acc[i][0]);
            acc[i][1] = f32x2_fma(ad, bq1, acc[i][1]);
        }
    }

#pragma unroll
    for (int i = 0; i < 8; i++) {
        int r = g * 128 + (ty << 3) + i;
        float2 v0 = f32x2_unpack(acc[i][0]);
        float2 v1 = f32x2_unpack(acc[i][1]);
        float4 o = make_float4(v0.x, v0.y, v1.x, v1.y);
        uint2 hv, lv;
        split4(o, hv, lv);
        int col = (j << 6) + (tx << 2);
        *reinterpret_cast<uint2*>(&Oh[r * DMODEL + col]) = hv;
        *reinterpret_cast<uint2*>(&Ol[r * DMODEL + col]) = lv;
    }
}

// ============================================================================
extern "C" void kernel_launch(void* const* d_in, const int* in_sizes, int n_in,
                              void* d_out, int out_size) {
    const float* x   = (const float*)d_in[0];
    const float* y   = (const float*)d_in[1];
    const float* q_w = (const float*)d_in[2];
    const float* q_b = (const float*)d_in[3];
    const float* k_w = (const float*)d_in[4];
    const float* k_b = (const float*)d_in[5];
    const float* v_w = (const float*)d_in[6];
    const float* v_b = (const float*)d_in[7];
    const float* o_w = (const float*)d_in[8];
    const float* o_b = (const float*)d_in[9];
    float* out = (float*)d_out;

    float *Qp, *Kp, *Vp, *Mpp, *Mp;
    cudaGetSymbolAddress((void**)&Qp, g_Q);
    cudaGetSymbolAddress((void**)&Kp, g_K);
    cudaGetSymbolAddress((void**)&Vp, g_V);
    cudaGetSymbolAddress((void**)&Mpp, g_Mpart);
    cudaGetSymbolAddress((void**)&Mp, g_M);

    __nv_bfloat16 *xh, *xl, *yh, *yl, *oh, *ol;
    __nv_bfloat16 *qwh, *qwl, *kwh, *kwl, *vwh, *vwl, *owh, *owl;
    cudaGetSymbolAddress((void**)&xh, g_xh);  cudaGetSymbolAddress((void**)&xl, g_xl);
    cudaGetSymbolAddress((void**)&yh, g_yh);  cudaGetSymbolAddress((void**)&yl, g_yl);
    cudaGetSymbolAddress((void**)&oh, g_oh);  cudaGetSymbolAddress((void**)&ol, g_ol);
    cudaGetSymbolAddress((void**)&qwh, g_qwh); cudaGetSymbolAddress((void**)&qwl, g_qwl);
    cudaGetSymbolAddress((void**)&kwh, g_kwh); cudaGetSymbolAddress((void**)&kwl, g_kwl);
    cudaGetSymbolAddress((void**)&vwh, g_vwh); cudaGetSymbolAddress((void**)&vwl, g_vwl);
    cudaGetSymbolAddress((void**)&owh, g_owh); cudaGetSymbolAddress((void**)&owl, g_owl);

    cudaFuncSetAttribute(gemm_qkv, cudaFuncAttributeMaxDynamicSharedMemorySize,
                         GS_TOTAL);
    cudaFuncSetAttribute(gemm_single, cudaFuncAttributeMaxDynamicSharedMemorySize,
                         GS_TOTAL);

    const int n4_act = MROWS * DMODEL / 4;    // 1048576
    const int n4_w = DMODEL * DMODEL / 4;     // 262144

    split_act<<<dim3(n4_act / 256, 2), 256>>>(x, y, xh, xl, yh, yl);
    split_w<<<dim3(n4_w / 256, 4), 256>>>(q_w, k_w, v_w, o_w,
                                          qwh, qwl, kwh, kwl, vwh, vwl, owh, owl);

    gemm_qkv<<<dim3(DMODEL / 256, MROWS / 128, 3), 256, GS_TOTAL>>>(
        xh, xl, yh, yl, qwh, qwl, kwh, kwl, vwh, vwl, q_b, k_b, v_b, Qp, Kp, Vp);

    compute_m_partial<<<dim3(8, 32), 256>>>(Kp, Vp, Mpp);
    reduce_m<<<512, 256>>>(Mpp, Mp);
    apply_m<<<dim3(16, 32), 256>>>(Qp, Mp, oh, ol);

    gemm_single<<<dim3(DMODEL / 256, MROWS / 128), 256, GS_TOTAL>>>(
        oh, ol, owh, owl, o_b, out);
}

// round 6
// speedup vs baseline: 2.3645x; 1.0234x over previous
#include <cuda_runtime.h>
#include <cuda_bf16.h>
#include <cstdint>

// ============================================================================
// Multihead_Attention (no-softmax => fully linear) on sm_100 (generic PTX).
//   split x,y,weights into bf16 hi/lo (fused launches)
//   Q,K,V = one merged 3-GEMM launch (mma.sync bf16 3-term split, fp32 accum)
//   Mg[64,64] = (1/32) Kg^T Vg  (partial + reduce, fp32)
//   O rows(g) = Qg @ blockdiag(Mg)  -> emitted directly as bf16 hi/lo
//   out = O @ o_w^T + o_b  (split GEMM)
// R6 == R5 (infra failure on R5 bench): 4-stage cp.async pipeline + ldmatrix
//   fragment double-buffering; compute_m_partial at grid (16,32).
// ============================================================================

#define MROWS 4096
#define DMODEL 1024

// fp32 intermediates
__device__ float g_Q[MROWS * DMODEL];
__device__ float g_K[MROWS * DMODEL];
__device__ float g_V[MROWS * DMODEL];
__device__ float g_Mpart[16 * 32 * 64 * 64];
__device__ float g_M[32 * 64 * 64];

// bf16 split operands
__device__ __nv_bfloat16 g_xh[MROWS * DMODEL], g_xl[MROWS * DMODEL];
__device__ __nv_bfloat16 g_yh[MROWS * DMODEL], g_yl[MROWS * DMODEL];
__device__ __nv_bfloat16 g_oh[MROWS * DMODEL], g_ol[MROWS * DMODEL];
__device__ __nv_bfloat16 g_qwh[DMODEL * DMODEL], g_qwl[DMODEL * DMODEL];
__device__ __nv_bfloat16 g_kwh[DMODEL * DMODEL], g_kwl[DMODEL * DMODEL];
__device__ __nv_bfloat16 g_vwh[DMODEL * DMODEL], g_vwl[DMODEL * DMODEL];
__device__ __nv_bfloat16 g_owh[DMODEL * DMODEL], g_owl[DMODEL * DMODEL];

// ---------------- generic PTX helpers ---------------------------------------
__device__ __forceinline__ uint32_t smem_u32(const void* p) {
    uint32_t a;
    asm("{ .reg .u64 t; cvta.to.shared.u64 t, %1; cvt.u32.u64 %0, t; }"
        : "=r"(a) : "l"(p));
    return a;
}
__device__ __forceinline__ void cp16(uint32_t dst, const void* src) {
    asm volatile("cp.async.cg.shared.global [%0], [%1], 16;"
                 :: "r"(dst), "l"(src) : "memory");
}
__device__ __forceinline__ void ldsm4(uint32_t (&r)[4], uint32_t addr) {
    asm volatile("ldmatrix.sync.aligned.m8n8.x4.shared.b16 {%0,%1,%2,%3}, [%4];"
                 : "=r"(r[0]), "=r"(r[1]), "=r"(r[2]), "=r"(r[3]) : "r"(addr));
}
__device__ __forceinline__ void mma16816(float (&d)[4], const uint32_t (&a)[4],
                                         uint32_t b0, uint32_t b1) {
    asm volatile(
        "mma.sync.aligned.m16n8k16.row.col.f32.bf16.bf16.f32 "
        "{%0,%1,%2,%3}, {%4,%5,%6,%7}, {%8,%9}, {%0,%1,%2,%3};"
        : "+f"(d[0]), "+f"(d[1]), "+f"(d[2]), "+f"(d[3])
        : "r"(a[0]), "r"(a[1]), "r"(a[2]), "r"(a[3]), "r"(b0), "r"(b1));
}

// ---------------- f32x2 helpers ---------------------------------------------
__device__ __forceinline__ unsigned long long f32x2_dup(float x) {
    unsigned long long r; asm("mov.b64 %0, {%1, %1};" : "=l"(r) : "f"(x)); return r;
}
__device__ __forceinline__ unsigned long long f32x2_pack(float x, float y) {
    unsigned long long r; asm("mov.b64 %0, {%1, %2};" : "=l"(r) : "f"(x), "f"(y)); return r;
}
__device__ __forceinline__ unsigned long long f32x2_fma(unsigned long long a,
                                                        unsigned long long b,
                                                        unsigned long long c) {
    unsigned long long d;
    asm("fma.rn.f32x2 %0, %1, %2, %3;" : "=l"(d) : "l"(a), "l"(b), "l"(c));
    return d;
}
__device__ __forceinline__ float2 f32x2_unpack(unsigned long long v) {
    float2 r; asm("mov.b64 {%0, %1}, %2;" : "=f"(r.x), "=f"(r.y) : "l"(v)); return r;
}

// pack 4 fp32 -> bf16 hi uint2 + lo uint2
__device__ __forceinline__ void split4(float4 v, uint2& hv, uint2& lv) {
    __nv_bfloat16 h0 = __float2bfloat16(v.x), h1 = __float2bfloat16(v.y);
    __nv_bfloat16 h2 = __float2bfloat16(v.z), h3 = __float2bfloat16(v.w);
    __nv_bfloat16 l0 = __float2bfloat16(v.x - __bfloat162float(h0));
    __nv_bfloat16 l1 = __float2bfloat16(v.y - __bfloat162float(h1));
    __nv_bfloat16 l2 = __float2bfloat16(v.z - __bfloat162float(h2));
    __nv_bfloat16 l3 = __float2bfloat16(v.w - __bfloat162float(h3));
    __nv_bfloat162 hp0 = {h0, h1}, hp1 = {h2, h3};
    __nv_bfloat162 lp0 = {l0, l1}, lp1 = {l2, l3};
    hv.x = *reinterpret_cast<uint32_t*>(&hp0); hv.y = *reinterpret_cast<uint32_t*>(&hp1);
    lv.x = *reinterpret_cast<uint32_t*>(&lp0); lv.y = *reinterpret_cast<uint32_t*>(&lp1);
}

// ============================================================================
// fused activation split: y-dim selects x vs y
// ============================================================================
__global__ __launch_bounds__(256)
void split_act(const float* __restrict__ x, const float* __restrict__ y,
               __nv_bfloat16* __restrict__ xh, __nv_bfloat16* __restrict__ xl,
               __nv_bfloat16* __restrict__ yh, __nv_bfloat16* __restrict__ yl) {
    const float* src = blockIdx.y ? y : x;
    __nv_bfloat16* hi = blockIdx.y ? yh : xh;
    __nv_bfloat16* lo = blockIdx.y ? yl : xl;
    int i = blockIdx.x * 256 + threadIdx.x;
    float4 v = reinterpret_cast<const float4*>(src)[i];
    uint2 hv, lv;
    split4(v, hv, lv);
    reinterpret_cast<uint2*>(hi)[i] = hv;
    reinterpret_cast<uint2*>(lo)[i] = lv;
}

__global__ __launch_bounds__(256)
void split_w(const float* __restrict__ w0, const float* __restrict__ w1,
             const float* __restrict__ w2, const float* __restrict__ w3,
             __nv_bfloat16* __restrict__ h0, __nv_bfloat16* __restrict__ l0,
             __nv_bfloat16* __restrict__ h1, __nv_bfloat16* __restrict__ l1,
             __nv_bfloat16* __restrict__ h2, __nv_bfloat16* __restrict__ l2,
             __nv_bfloat16* __restrict__ h3, __nv_bfloat16* __restrict__ l3) {
    const float* srcs[4] = {w0, w1, w2, w3};
    __nv_bfloat16* his[4] = {h0, h1, h2, h3};
    __nv_bfloat16* los[4] = {l0, l1, l2, l3};
    const float* src = srcs[blockIdx.y];
    __nv_bfloat16* hi = his[blockIdx.y];
    __nv_bfloat16* lo = los[blockIdx.y];
    int i = blockIdx.x * 256 + threadIdx.x;
    float4 v = reinterpret_cast<const float4*>(src)[i];
    uint2 hv, lv;
    split4(v, hv, lv);
    reinterpret_cast<uint2*>(hi)[i] = hv;
    reinterpret_cast<uint2*>(lo)[i] = lv;
}

// ============================================================================
// Split GEMM core via mma.sync: C[4096,1024] = A @ W^T + bias
// CTA tile 128(M) x 256(N), BK=64, 4-stage cp.async, 8 warps (warp 64x64).
// K-extended mainloop: 48 iters = 3 passes x 16  (AhWh, AlWh, AhWl).
// SMEM rows padded to 72 halves (144B) -> conflict-free ldmatrix phases.
// Fragment double-buffering: ldsm(kc+1) overlaps mma(kc).
// ============================================================================
#define GS_NSTAGE 4
#define GS_A_STAGE 18432              // 128*144
#define GS_B_BASE  (GS_NSTAGE * GS_A_STAGE)       // 73728
#define GS_B_STAGE 36864              // 256*144
#define GS_TOTAL   (GS_B_BASE + GS_NSTAGE * GS_B_STAGE)   // 221184

__device__ __forceinline__
void gemm_core(const __nv_bfloat16* __restrict__ Ah, const __nv_bfloat16* __restrict__ Al,
               const __nv_bfloat16* __restrict__ Wh, const __nv_bfloat16* __restrict__ Wl,
               const float* __restrict__ bias, float* __restrict__ C,
               char* smem, float* biasS, int m0, int n0) {
    const uint32_t sbase = smem_u32(smem);
    const int tid = threadIdx.x;
    const int lane = tid & 31;
    const int wid = tid >> 5;

    biasS[tid] = bias[n0 + tid];

    auto load_stage = [&](int it, int s) {
        const int p = it >> 4;                 // pass 0/1/2
        const int kcol = (it & 15) << 6;       // K offset (64 per stage)
        const __nv_bfloat16* ap = (p == 1) ? Al : Ah;
        const __nv_bfloat16* wp = (p == 2) ? Wl : Wh;
        const uint32_t sa = sbase + s * GS_A_STAGE;
        const uint32_t sb = sbase + GS_B_BASE + s * GS_B_STAGE;
#pragma unroll
        for (int u = 0; u < 4; u++) {
            int idx = tid + (u << 8);
            int r = idx >> 3, c = idx & 7;
            cp16(sa + r * 144 + c * 16, ap + (m0 + r) * DMODEL + kcol + c * 8);
        }
#pragma unroll
        for (int u = 0; u < 8; u++) {
            int idx = tid + (u << 8);
            int r = idx >> 3, c = idx & 7;
            cp16(sb + r * 144 + c * 16, wp + (n0 + r) * DMODEL + kcol + c * 8);
        }
    };

    load_stage(0, 0);
    asm volatile("cp.async.commit_group;" ::: "memory");
    load_stage(1, 1);
    asm volatile("cp.async.commit_group;" ::: "memory");
    load_stage(2, 2);
    asm volatile("cp.async.commit_group;" ::: "memory");

    float d[4][8][4];
#pragma unroll
    for (int mf = 0; mf < 4; mf++)
#pragma unroll
        for (int nf = 0; nf < 8; nf++)
#pragma unroll
            for (int q = 0; q < 4; q++) d[mf][nf][q] = 0.f;

    const int warpM = (wid >> 2) << 6;   // 0 or 64
    const int warpN = (wid & 3) << 6;    // 0,64,128,192
    const uint32_t aLane = (warpM + (lane & 15)) * 144 + (lane >> 4) * 16;
    const uint32_t bLane = (warpN + ((lane >> 4) & 1) * 8 + (lane & 7)) * 144 +
                           ((lane >> 3) & 1) * 16;

    uint32_t a[2][4][4], b[2][4][4];

    for (int it = 0; it < 48; ++it) {
        const int buf = it & 3;
        if (it < 46)
            asm volatile("cp.async.wait_group 2;" ::: "memory");
        else if (it == 46)
            asm volatile("cp.async.wait_group 1;" ::: "memory");
        else
            asm volatile("cp.async.wait_group 0;" ::: "memory");
        __syncthreads();
        if (it + 3 < 48) {
            load_stage(it + 3, (it + 3) & 3);
            asm volatile("cp.async.commit_group;" ::: "memory");
        }
        const uint32_t sa = sbase + buf * GS_A_STAGE + aLane;
        const uint32_t sb = sbase + GS_B_BASE + buf * GS_B_STAGE + bLane;
        const uint32_t sa0 = sa, sa1 = sa + 2304, sa2 = sa + 4608, sa3 = sa + 6912;
        const uint32_t sb0 = sb, sb1 = sb + 2304, sb2 = sb + 4608, sb3 = sb + 6912;

        // prefetch kc=0 fragments
        ldsm4(a[0][0], sa0); ldsm4(a[0][1], sa1);
        ldsm4(a[0][2], sa2); ldsm4(a[0][3], sa3);
        ldsm4(b[0][0], sb0); ldsm4(b[0][1], sb1);
        ldsm4(b[0][2], sb2); ldsm4(b[0][3], sb3);

#pragma unroll
        for (int kc = 0; kc < 4; kc++) {
            const int cur = kc & 1, nxt = cur ^ 1;
            if (kc < 3) {
                const uint32_t ko = (kc + 1) * 32;
                ldsm4(a[nxt][0], sa0 + ko); ldsm4(a[nxt][1], sa1 + ko);
                ldsm4(a[nxt][2], sa2 + ko); ldsm4(a[nxt][3], sa3 + ko);
                ldsm4(b[nxt][0], sb0 + ko); ldsm4(b[nxt][1], sb1 + ko);
                ldsm4(b[nxt][2], sb2 + ko); ldsm4(b[nxt][3], sb3 + ko);
            }
#pragma unroll
            for (int mf = 0; mf < 4; mf++)
#pragma unroll
                for (int nf = 0; nf < 8; nf++)
                    mma16816(d[mf][nf], a[cur][mf], b[cur][nf >> 1][(nf & 1) * 2],
                             b[cur][nf >> 1][(nf & 1) * 2 + 1]);
        }
    }

    const int rsub = lane >> 2;
    const int csub = (lane & 3) * 2;
#pragma unroll
    for (int mf = 0; mf < 4; mf++) {
#pragma unroll
        for (int nf = 0; nf < 8; nf++) {
            const int row = m0 + warpM + mf * 16 + rsub;
            const int colL = warpN + nf * 8 + csub;
            const float b0 = biasS[colL], b1 = biasS[colL + 1];
            float2 v0 = make_float2(d[mf][nf][0] + b0, d[mf][nf][1] + b1);
            float2 v1 = make_float2(d[mf][nf][2] + b0, d[mf][nf][3] + b1);
            *reinterpret_cast<float2*>(&C[(size_t)row * DMODEL + n0 + colL]) = v0;
            *reinterpret_cast<float2*>(&C[(size_t)(row + 8) * DMODEL + n0 + colL]) = v1;
        }
    }
}

// merged Q/K/V projections: blockIdx.z selects the GEMM
__global__ __launch_bounds__(256, 1)
void gemm_qkv(const __nv_bfloat16* __restrict__ xh, const __nv_bfloat16* __restrict__ xl,
              const __nv_bfloat16* __restrict__ yh, const __nv_bfloat16* __restrict__ yl,
              const __nv_bfloat16* __restrict__ qwh, const __nv_bfloat16* __restrict__ qwl,
              const __nv_bfloat16* __restrict__ kwh, const __nv_bfloat16* __restrict__ kwl,
              const __nv_bfloat16* __restrict__ vwh, const __nv_bfloat16* __restrict__ vwl,
              const float* __restrict__ q_b, const float* __restrict__ k_b,
              const float* __restrict__ v_b,
              float* __restrict__ Q, float* __restrict__ K, float* __restrict__ V) {
    extern __shared__ __align__(128) char smem[];
    __shared__ float biasS[256];
    const int z = blockIdx.z;
    const __nv_bfloat16* Ah = (z == 2) ? yh : xh;
    const __nv_bfloat16* Al = (z == 2) ? yl : xl;
    const __nv_bfloat16* Wh = (z == 0) ? qwh : (z == 1) ? kwh : vwh;
    const __nv_bfloat16* Wl = (z == 0) ? qwl : (z == 1) ? kwl : vwl;
    const float* bias = (z == 0) ? q_b : (z == 1) ? k_b : v_b;
    float* C = (z == 0) ? Q : (z == 1) ? K : V;
    gemm_core(Ah, Al, Wh, Wl, bias, C, smem, biasS,
              blockIdx.y << 7, blockIdx.x << 8);
}

__global__ __launch_bounds__(256, 1)
void gemm_single(const __nv_bfloat16* __restrict__ Ah, const __nv_bfloat16* __restrict__ Al,
                 const __nv_bfloat16* __restrict__ Wh, const __nv_bfloat16* __restrict__ Wl,
                 const float* __restrict__ bias, float* __restrict__ C) {
    extern __shared__ __align__(128) char smem[];
    __shared__ float biasS[256];
    gemm_core(Ah, Al, Wh, Wl, bias, C, smem, biasS,
              blockIdx.y << 7, blockIdx.x << 8);
}

// ============================================================================
// compute_m_partial: Mpart[s][g] = sum over t in [s*128,(s+1)*128) Kg[t]^T Vg[t]
// grid (16, 32), 256 threads, 4x4 per thread.
// ============================================================================
__global__ __launch_bounds__(256)
void compute_m_partial(const float* __restrict__ Kb, const float* __restrict__ Vb,
                       float* __restrict__ Mpart) {
    const int s = blockIdx.x;
    const int g = blockIdx.y;
    __shared__ float Ks[32][64];
    __shared__ float Vs[32][64];

    const int tid = threadIdx.x;
    const int tx = tid & 15;
    const int ty = tid >> 4;

    const float* Kg = Kb + g * 131072 + s * 128 * 64;
    const float* Vg = Vb + g * 131072 + s * 128 * 64;

    unsigned long long acc[4][2];
#pragma unroll
    for (int i = 0; i < 4; i++) { acc[i][0] = 0ull; acc[i][1] = 0ull; }

    for (int t0 = 0; t0 < 128; t0 += 32) {
#pragma unroll
        for (int sr = 0; sr < 2; sr++) {
            int idx = tid + (sr << 8);
            int tt = idx >> 4;
            int d4 = (idx & 15) << 2;
            *reinterpret_cast<float4*>(&Ks[tt][d4]) =
                *reinterpret_cast<const float4*>(&Kg[(t0 + tt) * 64 + d4]);
            *reinterpret_cast<float4*>(&Vs[tt][d4]) =
                *reinterpret_cast<const float4*>(&Vg[(t0 + tt) * 64 + d4]);
        }
        __syncthreads();
#pragma unroll 8
        for (int tt = 0; tt < 32; tt++) {
            float4 a = *reinterpret_cast<const float4*>(&Ks[tt][ty << 2]);
            float4 b = *reinterpret_cast<const float4*>(&Vs[tt][tx << 2]);
            unsigned long long bq0 = f32x2_pack(b.x, b.y);
            unsigned long long bq1 = f32x2_pack(b.z, b.w);
            float av[4] = {a.x, a.y, a.z, a.w};
#pragma unroll
            for (int i = 0; i < 4; i++) {
                unsigned long long ad = f32x2_dup(av[i]);
                acc[i][0] = f32x2_fma(ad, bq0, acc[i][0]);
                acc[i][1] = f32x2_fma(ad, bq1, acc[i][1]);
            }
        }
        __syncthreads();
    }

#pragma unroll
    for (int i = 0; i < 4; i++) {
        float2 v0 = f32x2_unpack(acc[i][0]);
        float2 v1 = f32x2_unpack(acc[i][1]);
        int d = (ty << 2) + i;
        int dp = tx << 2;
        float4 o = make_float4(v0.x, v0.y, v1.x, v1.y);
        *reinterpret_cast<float4*>(&Mpart[(s * 32 + g) * 4096 + d * 64 + dp]) = o;
    }
}

__global__ __launch_bounds__(256)
void reduce_m(const float* __restrict__ Mpart, float* __restrict__ M) {
    int i = blockIdx.x * 256 + threadIdx.x;
    float acc = 0.f;
#pragma unroll
    for (int s = 0; s < 16; s++) acc += Mpart[s * 131072 + i];
    M[i] = acc * 0.03125f;
}

// ============================================================================
// apply_m: O[r, j*64+d'] = sum_d Q[r, j*64+d] * M[g][d][d'],  g = r/128
// Emits bf16 hi/lo directly (feeds output-projection GEMM).
// ============================================================================
__global__ __launch_bounds__(256)
void apply_m(const float* __restrict__ Qb, const float* __restrict__ Mb,
             __nv_bfloat16* __restrict__ Oh, __nv_bfloat16* __restrict__ Ol) {
    const int j = blockIdx.x;
    const int g = blockIdx.y;

    __shared__ float Qs[64][128];
    __shared__ float Ms[64][64];

    const int tid = threadIdx.x;
    const int tx = tid & 15;
    const int ty = tid >> 4;

#pragma unroll
    for (int s = 0; s < 4; s++) {
        int idx = tid + (s << 8);
        *reinterpret_cast<float4*>(&Ms[idx >> 4][(idx & 15) << 2]) =
            *reinterpret_cast<const float4*>(&Mb[g * 4096 + idx * 4]);
    }
#pragma unroll
    for (int s = 0; s < 8; s++) {
        int idx = tid + (s << 8);
        int r = idx & 127;
        int d4 = (idx >> 7) << 2;
        float4 v = *reinterpret_cast<const float4*>(
            &Qb[(g * 128 + r) * DMODEL + (j << 6) + d4]);
        Qs[d4 + 0][r] = v.x; Qs[d4 + 1][r] = v.y;
        Qs[d4 + 2][r] = v.z; Qs[d4 + 3][r] = v.w;
    }
    __syncthreads();

    unsigned long long acc[8][2];
#pragma unroll
    for (int i = 0; i < 8; i++) { acc[i][0] = 0ull; acc[i][1] = 0ull; }

#pragma unroll 4
    for (int d = 0; d < 64; d++) {
        float4 a0 = *reinterpret_cast<const float4*>(&Qs[d][ty << 3]);
        float4 a1 = *reinterpret_cast<const float4*>(&Qs[d][(ty << 3) + 4]);
        float4 b = *reinterpret_cast<const float4*>(&Ms[d][tx << 2]);
        unsigned long long bq0 = f32x2_pack(b.x, b.y);
        unsigned long long bq1 = f32x2_pack(b.z, b.w);
        float av[8] = {a0.x, a0.y, a0.z, a0.w, a1.x, a1.y, a1.z, a1.w};
#pragma unroll
        for (int i = 0; i < 8; i++) {
            unsigned long long ad = f32x2_dup(av[i]);
            acc[i][0] = f32x2_fma(ad, bq0, acc[i][0]);
            acc[i][1] = f32x2_fma(ad, bq1, acc[i][1]);
        }
    }

#pragma unroll
    for (int i = 0; i < 8; i++) {
        int r = g * 128 + (ty << 3) + i;
        float2 v0 = f32x2_unpack(acc[i][0]);
        float2 v1 = f32x2_unpack(acc[i][1]);
        float4 o = make_float4(v0.x, v0.y, v1.x, v1.y);
        uint2 hv, lv;
        split4(o, hv, lv);
        int col = (j << 6) + (tx << 2);
        *reinterpret_cast<uint2*>(&Oh[r * DMODEL + col]) = hv;
        *reinterpret_cast<uint2*>(&Ol[r * DMODEL + col]) = lv;
    }
}

// ============================================================================
extern "C" void kernel_launch(void* const* d_in, const int* in_sizes, int n_in,
                              void* d_out, int out_size) {
    const float* x   = (const float*)d_in[0];
    const float* y   = (const float*)d_in[1];
    const float* q_w = (const float*)d_in[2];
    const float* q_b = (const float*)d_in[3];
    const float* k_w = (const float*)d_in[4];
    const float* k_b = (const float*)d_in[5];
    const float* v_w = (const float*)d_in[6];
    const float* v_b = (const float*)d_in[7];
    const float* o_w = (const float*)d_in[8];
    const float* o_b = (const float*)d_in[9];
    float* out = (float*)d_out;

    float *Qp, *Kp, *Vp, *Mpp, *Mp;
    cudaGetSymbolAddress((void**)&Qp, g_Q);
    cudaGetSymbolAddress((void**)&Kp, g_K);
    cudaGetSymbolAddress((void**)&Vp, g_V);
    cudaGetSymbolAddress((void**)&Mpp, g_Mpart);
    cudaGetSymbolAddress((void**)&Mp, g_M);

    __nv_bfloat16 *xh, *xl, *yh, *yl, *oh, *ol;
    __nv_bfloat16 *qwh, *qwl, *kwh, *kwl, *vwh, *vwl, *owh, *owl;
    cudaGetSymbolAddress((void**)&xh, g_xh);  cudaGetSymbolAddress((void**)&xl, g_xl);
    cudaGetSymbolAddress((void**)&yh, g_yh);  cudaGetSymbolAddress((void**)&yl, g_yl);
    cudaGetSymbolAddress((void**)&oh, g_oh);  cudaGetSymbolAddress((void**)&ol, g_ol);
    cudaGetSymbolAddress((void**)&qwh, g_qwh); cudaGetSymbolAddress((void**)&qwl, g_qwl);
    cudaGetSymbolAddress((void**)&kwh, g_kwh); cudaGetSymbolAddress((void**)&kwl, g_kwl);
    cudaGetSymbolAddress((void**)&vwh, g_vwh); cudaGetSymbolAddress((void**)&vwl, g_vwl);
    cudaGetSymbolAddress((void**)&owh, g_owh); cudaGetSymbolAddress((void**)&owl, g_owl);

    cudaFuncSetAttribute(gemm_qkv, cudaFuncAttributeMaxDynamicSharedMemorySize,
                         GS_TOTAL);
    cudaFuncSetAttribute(gemm_single, cudaFuncAttributeMaxDynamicSharedMemorySize,
                         GS_TOTAL);

    const int n4_act = MROWS * DMODEL / 4;    // 1048576
    const int n4_w = DMODEL * DMODEL / 4;     // 262144

    split_act<<<dim3(n4_act / 256, 2), 256>>>(x, y, xh, xl, yh, yl);
    split_w<<<dim3(n4_w / 256, 4), 256>>>(q_w, k_w, v_w, o_w,
                                          qwh, qwl, kwh, kwl, vwh, vwl, owh, owl);

    gemm_qkv<<<dim3(DMODEL / 256, MROWS / 128, 3), 256, GS_TOTAL>>>(
        xh, xl, yh, yl, qwh, qwl, kwh, kwl, vwh, vwl, q_b, k_b, v_b, Qp, Kp, Vp);

    compute_m_partial<<<dim3(16, 32), 256>>>(Kp, Vp, Mpp);
    reduce_m<<<512, 256>>>(Mpp, Mp);
    apply_m<<<dim3(16, 32), 256>>>(Qp, Mp, oh, ol);

    gemm_single<<<dim3(DMODEL / 256, MROWS / 128), 256, GS_TOTAL>>>(
        oh, ol, owh, owl, o_b, out);
}

// round 9
// speedup vs baseline: 3.2860x; 1.3898x over previous
#include <cuda_runtime.h>
#include <cuda_bf16.h>
#include <cuda_fp16.h>
#include <cstdint>

// ============================================================================
// Multihead_Attention (no-softmax => fully linear) on sm_100 (generic PTX).
// R9 == R7 == R8 (broker infra failed twice; source audited clean):
//     QKV projections via fp16 2-limb asymmetric split (A = Ah+Al fp16 exact,
//     W single fp16) -> 2/3 the MMA instructions of the bf16 3-pass.
//     Output GEMM stays bf16 3-pass (accuracy anchor).
//     Legacy mma.sync pipe is the binder (~512 MAC/cyc/SM) per R6 evidence.
// ============================================================================

#define MROWS 4096
#define DMODEL 1024

// fp32 intermediates
__device__ float g_Q[MROWS * DMODEL];
__device__ float g_K[MROWS * DMODEL];
__device__ float g_V[MROWS * DMODEL];
__device__ float g_Mpart[32 * 32 * 64 * 64];
__device__ float g_M[32 * 64 * 64];

// fp16 split operands (QKV path)
__device__ __half g_xh[MROWS * DMODEL], g_xl[MROWS * DMODEL];
__device__ __half g_yh[MROWS * DMODEL], g_yl[MROWS * DMODEL];
__device__ __half g_qwh[DMODEL * DMODEL];
__device__ __half g_kwh[DMODEL * DMODEL];
__device__ __half g_vwh[DMODEL * DMODEL];

// bf16 split operands (output-projection path, 3-pass)
__device__ __nv_bfloat16 g_oh[MROWS * DMODEL], g_ol[MROWS * DMODEL];
__device__ __nv_bfloat16 g_owh[DMODEL * DMODEL], g_owl[DMODEL * DMODEL];

// ---------------- generic PTX helpers ---------------------------------------
__device__ __forceinline__ uint32_t smem_u32(const void* p) {
    uint32_t a;
    asm("{ .reg .u64 t; cvta.to.shared.u64 t, %1; cvt.u32.u64 %0, t; }"
        : "=r"(a) : "l"(p));
    return a;
}
__device__ __forceinline__ void cp16(uint32_t dst, const void* src) {
    asm volatile("cp.async.cg.shared.global [%0], [%1], 16;"
                 :: "r"(dst), "l"(src) : "memory");
}
__device__ __forceinline__ void ldsm4(uint32_t (&r)[4], uint32_t addr) {
    asm volatile("ldmatrix.sync.aligned.m8n8.x4.shared.b16 {%0,%1,%2,%3}, [%4];"
                 : "=r"(r[0]), "=r"(r[1]), "=r"(r[2]), "=r"(r[3]) : "r"(addr));
}
__device__ __forceinline__ void mma_bf16(float (&d)[4], const uint32_t (&a)[4],
                                         uint32_t b0, uint32_t b1) {
    asm volatile(
        "mma.sync.aligned.m16n8k16.row.col.f32.bf16.bf16.f32 "
        "{%0,%1,%2,%3}, {%4,%5,%6,%7}, {%8,%9}, {%0,%1,%2,%3};"
        : "+f"(d[0]), "+f"(d[1]), "+f"(d[2]), "+f"(d[3])
        : "r"(a[0]), "r"(a[1]), "r"(a[2]), "r"(a[3]), "r"(b0), "r"(b1));
}
__device__ __forceinline__ void mma_f16(float (&d)[4], const uint32_t (&a)[4],
                                        uint32_t b0, uint32_t b1) {
    asm volatile(
        "mma.sync.aligned.m16n8k16.row.col.f32.f16.f16.f32 "
        "{%0,%1,%2,%3}, {%4,%5,%6,%7}, {%8,%9}, {%0,%1,%2,%3};"
        : "+f"(d[0]), "+f"(d[1]), "+f"(d[2]), "+f"(d[3])
        : "r"(a[0]), "r"(a[1]), "r"(a[2]), "r"(a[3]), "r"(b0), "r"(b1));
}

// ---------------- f32x2 helpers ---------------------------------------------
__device__ __forceinline__ unsigned long long f32x2_dup(float x) {
    unsigned long long r; asm("mov.b64 %0, {%1, %1};" : "=l"(r) : "f"(x)); return r;
}
__device__ __forceinline__ unsigned long long f32x2_pack(float x, float y) {
    unsigned long long r; asm("mov.b64 %0, {%1, %2};" : "=l"(r) : "f"(x), "f"(y)); return r;
}
__device__ __forceinline__ unsigned long long f32x2_fma(unsigned long long a,
                                                        unsigned long long b,
                                                        unsigned long long c) {
    unsigned long long d;
    asm("fma.rn.f32x2 %0, %1, %2, %3;" : "=l"(d) : "l"(a), "l"(b), "l"(c));
    return d;
}
__device__ __forceinline__ float2 f32x2_unpack(unsigned long long v) {
    float2 r; asm("mov.b64 {%0, %1}, %2;" : "=f"(r.x), "=f"(r.y) : "l"(v)); return r;
}

// pack 4 fp32 -> bf16 hi uint2 + lo uint2
__device__ __forceinline__ void split4_bf16(float4 v, uint2& hv, uint2& lv) {
    __nv_bfloat16 h0 = __float2bfloat16(v.x), h1 = __float2bfloat16(v.y);
    __nv_bfloat16 h2 = __float2bfloat16(v.z), h3 = __float2bfloat16(v.w);
    __nv_bfloat16 l0 = __float2bfloat16(v.x - __bfloat162float(h0));
    __nv_bfloat16 l1 = __float2bfloat16(v.y - __bfloat162float(h1));
    __nv_bfloat16 l2 = __float2bfloat16(v.z - __bfloat162float(h2));
    __nv_bfloat16 l3 = __float2bfloat16(v.w - __bfloat162float(h3));
    __nv_bfloat162 hp0 = {h0, h1}, hp1 = {h2, h3};
    __nv_bfloat162 lp0 = {l0, l1}, lp1 = {l2, l3};
    hv.x = *reinterpret_cast<uint32_t*>(&hp0); hv.y = *reinterpret_cast<uint32_t*>(&hp1);
    lv.x = *reinterpret_cast<uint32_t*>(&lp0); lv.y = *reinterpret_cast<uint32_t*>(&lp1);
}

// pack 4 fp32 -> fp16 hi uint2 + lo uint2
__device__ __forceinline__ void split4_f16(float4 v, uint2& hv, uint2& lv) {
    __half h0 = __float2half_rn(v.x), h1 = __float2half_rn(v.y);
    __half h2 = __float2half_rn(v.z), h3 = __float2half_rn(v.w);
    __half l0 = __float2half_rn(v.x - __half2float(h0));
    __half l1 = __float2half_rn(v.y - __half2float(h1));
    __half l2 = __float2half_rn(v.z - __half2float(h2));
    __half l3 = __float2half_rn(v.w - __half2float(h3));
    __half2 hp0 = {h0, h1}, hp1 = {h2, h3};
    __half2 lp0 = {l0, l1}, lp1 = {l2, l3};
    hv.x = *reinterpret_cast<uint32_t*>(&hp0); hv.y = *reinterpret_cast<uint32_t*>(&hp1);
    lv.x = *reinterpret_cast<uint32_t*>(&lp0); lv.y = *reinterpret_cast<uint32_t*>(&lp1);
}

// ============================================================================
// splits
// ============================================================================
__global__ __launch_bounds__(256)
void split_act_f16(const float* __restrict__ x, const float* __restrict__ y,
                   __half* __restrict__ xh, __half* __restrict__ xl,
                   __half* __restrict__ yh, __half* __restrict__ yl) {
    const float* src = blockIdx.y ? y : x;
    __half* hi = blockIdx.y ? yh : xh;
    __half* lo = blockIdx.y ? yl : xl;
    int i = blockIdx.x * 256 + threadIdx.x;
    float4 v = reinterpret_cast<const float4*>(src)[i];
    uint2 hv, lv;
    split4_f16(v, hv, lv);
    reinterpret_cast<uint2*>(hi)[i] = hv;
    reinterpret_cast<uint2*>(lo)[i] = lv;
}

// q/k/v weights -> single fp16
__global__ __launch_bounds__(256)
void split_wqkv_f16(const float* __restrict__ w0, const float* __restrict__ w1,
                    const float* __restrict__ w2,
                    __half* __restrict__ h0, __half* __restrict__ h1,
                    __half* __restrict__ h2) {
    const float* src = (blockIdx.y == 0) ? w0 : (blockIdx.y == 1) ? w1 : w2;
    __half* hi = (blockIdx.y == 0) ? h0 : (blockIdx.y == 1) ? h1 : h2;
    int i = blockIdx.x * 256 + threadIdx.x;
    float4 v = reinterpret_cast<const float4*>(src)[i];
    __half a = __float2half_rn(v.x), b = __float2half_rn(v.y);
    __half c = __float2half_rn(v.z), d = __float2half_rn(v.w);
    __half2 p0 = {a, b}, p1 = {c, d};
    uint2 hv = {*reinterpret_cast<uint32_t*>(&p0), *reinterpret_cast<uint32_t*>(&p1)};
    reinterpret_cast<uint2*>(hi)[i] = hv;
}

// o_w -> bf16 hi/lo
__global__ __launch_bounds__(256)
void split_ow_bf16(const float* __restrict__ w,
                   __nv_bfloat16* __restrict__ hi, __nv_bfloat16* __restrict__ lo) {
    int i = blockIdx.x * 256 + threadIdx.x;
    float4 v = reinterpret_cast<const float4*>(w)[i];
    uint2 hv, lv;
    split4_bf16(v, hv, lv);
    reinterpret_cast<uint2*>(hi)[i] = hv;
    reinterpret_cast<uint2*>(lo)[i] = lv;
}

// ============================================================================
// fp16 2-limb QKV GEMM: C = (Ah + Al) @ Wh^T + bias
// CTA tile 128(M) x 256(N), BK=64, 3-stage cp.async, 8 warps (warp 64x64).
// 16 mainloop iters; per kc: 12 ldsm4 + 64 mma (2 limbs share one accum).
// SMEM rows 144B padded. Stage = Ah(18432) + Al(18432) + W(36864).
// ============================================================================
#define FQ_AS 18432
#define FQ_AL_BASE (3 * FQ_AS)            // 55296
#define FQ_W_BASE  (6 * FQ_AS)            // 110592
#define FQ_BS 36864
#define FQ_TOTAL (FQ_W_BASE + 3 * FQ_BS)  // 221184

__global__ __launch_bounds__(256, 1)
void gemm_qkv_f16(const __half* __restrict__ xh, const __half* __restrict__ xl,
                  const __half* __restrict__ yh, const __half* __restrict__ yl,
                  const __half* __restrict__ qwh, const __half* __restrict__ kwh,
                  const __half* __restrict__ vwh,
                  const float* __restrict__ q_b, const float* __restrict__ k_b,
                  const float* __restrict__ v_b,
                  float* __restrict__ Q, float* __restrict__ K, float* __restrict__ V) {
    extern __shared__ __align__(128) char smem[];
    __shared__ float biasS[256];
    const uint32_t sbase = smem_u32(smem);
    const int tid = threadIdx.x;
    const int lane = tid & 31;
    const int wid = tid >> 5;
    const int n0 = blockIdx.x << 8;
    const int m0 = blockIdx.y << 7;
    const int z = blockIdx.z;

    const __half* Ah = (z == 2) ? yh : xh;
    const __half* Al = (z == 2) ? yl : xl;
    const __half* Wh = (z == 0) ? qwh : (z == 1) ? kwh : vwh;
    const float* bias = (z == 0) ? q_b : (z == 1) ? k_b : v_b;
    float* C = (z == 0) ? Q : (z == 1) ? K : V;

    biasS[tid] = bias[n0 + tid];

    auto load_stage = [&](int kt, int s) {
        const int kcol = kt << 6;
        const uint32_t sah = sbase + s * FQ_AS;
        const uint32_t sal = sbase + FQ_AL_BASE + s * FQ_AS;
        const uint32_t sb = sbase + FQ_W_BASE + s * FQ_BS;
#pragma unroll
        for (int u = 0; u < 4; u++) {
            int idx = tid + (u << 8);
            int r = idx >> 3, c = idx & 7;
            cp16(sah + r * 144 + c * 16, Ah + (m0 + r) * DMODEL + kcol + c * 8);
            cp16(sal + r * 144 + c * 16, Al + (m0 + r) * DMODEL + kcol + c * 8);
        }
#pragma unroll
        for (int u = 0; u < 8; u++) {
            int idx = tid + (u << 8);
            int r = idx >> 3, c = idx & 7;
            cp16(sb + r * 144 + c * 16, Wh + (n0 + r) * DMODEL + kcol + c * 8);
        }
    };

    load_stage(0, 0);
    asm volatile("cp.async.commit_group;" ::: "memory");
    load_stage(1, 1);
    asm volatile("cp.async.commit_group;" ::: "memory");

    float d[4][8][4];
#pragma unroll
    for (int mf = 0; mf < 4; mf++)
#pragma unroll
        for (int nf = 0; nf < 8; nf++)
#pragma unroll
            for (int q = 0; q < 4; q++) d[mf][nf][q] = 0.f;

    const int warpM = (wid >> 2) << 6;
    const int warpN = (wid & 3) << 6;
    const uint32_t aLane = (warpM + (lane & 15)) * 144 + (lane >> 4) * 16;
    const uint32_t bLane = (warpN + ((lane >> 4) & 1) * 8 + (lane & 7)) * 144 +
                           ((lane >> 3) & 1) * 16;

    for (int it = 0; it < 16; ++it) {
        const int buf = it % 3;
        if (it < 15)
            asm volatile("cp.async.wait_group 1;" ::: "memory");
        else
            asm volatile("cp.async.wait_group 0;" ::: "memory");
        __syncthreads();
        if (it + 2 < 16) {
            load_stage(it + 2, (it + 2) % 3);
            asm volatile("cp.async.commit_group;" ::: "memory");
        }
        const uint32_t sah = sbase + buf * FQ_AS + aLane;
        const uint32_t sal = sbase + FQ_AL_BASE + buf * FQ_AS + aLane;
        const uint32_t sb = sbase + FQ_W_BASE + buf * FQ_BS + bLane;

#pragma unroll
        for (int kc = 0; kc < 4; kc++) {
            const uint32_t ko = kc * 32;
            uint32_t ah[4][4], al[4][4], bb[4][4];
#pragma unroll
            for (int mf = 0; mf < 4; mf++) ldsm4(ah[mf], sah + mf * 2304 + ko);
#pragma unroll
            for (int mf = 0; mf < 4; mf++) ldsm4(al[mf], sal + mf * 2304 + ko);
#pragma unroll
            for (int nf2 = 0; nf2 < 4; nf2++) ldsm4(bb[nf2], sb + nf2 * 2304 + ko);
#pragma unroll
            for (int mf = 0; mf < 4; mf++)
#pragma unroll
                for (int nf = 0; nf < 8; nf++)
                    mma_f16(d[mf][nf], ah[mf], bb[nf >> 1][(nf & 1) * 2],
                            bb[nf >> 1][(nf & 1) * 2 + 1]);
#pragma unroll
            for (int mf = 0; mf < 4; mf++)
#pragma unroll
                for (int nf = 0; nf < 8; nf++)
                    mma_f16(d[mf][nf], al[mf], bb[nf >> 1][(nf & 1) * 2],
                            bb[nf >> 1][(nf & 1) * 2 + 1]);
        }
    }

    const int rsub = lane >> 2;
    const int csub = (lane & 3) * 2;
#pragma unroll
    for (int mf = 0; mf < 4; mf++) {
#pragma unroll
        for (int nf = 0; nf < 8; nf++) {
            const int row = m0 + warpM + mf * 16 + rsub;
            const int colL = warpN + nf * 8 + csub;
            const float b0 = biasS[colL], b1 = biasS[colL + 1];
            float2 v0 = make_float2(d[mf][nf][0] + b0, d[mf][nf][1] + b1);
            float2 v1 = make_float2(d[mf][nf][2] + b0, d[mf][nf][3] + b1);
            *reinterpret_cast<float2*>(&C[(size_t)row * DMODEL + n0 + colL]) = v0;
            *reinterpret_cast<float2*>(&C[(size_t)(row + 8) * DMODEL + n0 + colL]) = v1;
        }
    }
}

// ============================================================================
// bf16 3-pass GEMM (R6 core) for the output projection.
// ============================================================================
#define GS_NSTAGE 4
#define GS_A_STAGE 18432
#define GS_B_BASE  (GS_NSTAGE * GS_A_STAGE)
#define GS_B_STAGE 36864
#define GS_TOTAL   (GS_B_BASE + GS_NSTAGE * GS_B_STAGE)   // 221184

__global__ __launch_bounds__(256, 1)
void gemm_out_bf16(const __nv_bfloat16* __restrict__ Ah, const __nv_bfloat16* __restrict__ Al,
                   const __nv_bfloat16* __restrict__ Wh, const __nv_bfloat16* __restrict__ Wl,
                   const float* __restrict__ bias, float* __restrict__ C) {
    extern __shared__ __align__(128) char smem[];
    __shared__ float biasS[256];
    const uint32_t sbase = smem_u32(smem);
    const int tid = threadIdx.x;
    const int lane = tid & 31;
    const int wid = tid >> 5;
    const int n0 = blockIdx.x << 8;
    const int m0 = blockIdx.y << 7;

    biasS[tid] = bias[n0 + tid];

    auto load_stage = [&](int it, int s) {
        const int p = it >> 4;
        const int kcol = (it & 15) << 6;
        const __nv_bfloat16* ap = (p == 1) ? Al : Ah;
        const __nv_bfloat16* wp = (p == 2) ? Wl : Wh;
        const uint32_t sa = sbase + s * GS_A_STAGE;
        const uint32_t sb = sbase + GS_B_BASE + s * GS_B_STAGE;
#pragma unroll
        for (int u = 0; u < 4; u++) {
            int idx = tid + (u << 8);
            int r = idx >> 3, c = idx & 7;
            cp16(sa + r * 144 + c * 16, ap + (m0 + r) * DMODEL + kcol + c * 8);
        }
#pragma unroll
        for (int u = 0; u < 8; u++) {
            int idx = tid + (u << 8);
            int r = idx >> 3, c = idx & 7;
            cp16(sb + r * 144 + c * 16, wp + (n0 + r) * DMODEL + kcol + c * 8);
        }
    };

    load_stage(0, 0);
    asm volatile("cp.async.commit_group;" ::: "memory");
    load_stage(1, 1);
    asm volatile("cp.async.commit_group;" ::: "memory");
    load_stage(2, 2);
    asm volatile("cp.async.commit_group;" ::: "memory");

    float d[4][8][4];
#pragma unroll
    for (int mf = 0; mf < 4; mf++)
#pragma unroll
        for (int nf = 0; nf < 8; nf++)
#pragma unroll
            for (int q = 0; q < 4; q++) d[mf][nf][q] = 0.f;

    const int warpM = (wid >> 2) << 6;
    const int warpN = (wid & 3) << 6;
    const uint32_t aLane = (warpM + (lane & 15)) * 144 + (lane >> 4) * 16;
    const uint32_t bLane = (warpN + ((lane >> 4) & 1) * 8 + (lane & 7)) * 144 +
                           ((lane >> 3) & 1) * 16;

    uint32_t a[2][4][4], b[2][4][4];

    for (int it = 0; it < 48; ++it) {
        const int buf = it & 3;
        if (it < 46)
            asm volatile("cp.async.wait_group 2;" ::: "memory");
        else if (it == 46)
            asm volatile("cp.async.wait_group 1;" ::: "memory");
        else
            asm volatile("cp.async.wait_group 0;" ::: "memory");
        __syncthreads();
        if (it + 3 < 48) {
            load_stage(it + 3, (it + 3) & 3);
            asm volatile("cp.async.commit_group;" ::: "memory");
        }
        const uint32_t sa = sbase + buf * GS_A_STAGE + aLane;
        const uint32_t sb = sbase + GS_B_BASE + buf * GS_B_STAGE + bLane;
        const uint32_t sa0 = sa, sa1 = sa + 2304, sa2 = sa + 4608, sa3 = sa + 6912;
        const uint32_t sb0 = sb, sb1 = sb + 2304, sb2 = sb + 4608, sb3 = sb + 6912;

        ldsm4(a[0][0], sa0); ldsm4(a[0][1], sa1);
        ldsm4(a[0][2], sa2); ldsm4(a[0][3], sa3);
        ldsm4(b[0][0], sb0); ldsm4(b[0][1], sb1);
        ldsm4(b[0][2], sb2); ldsm4(b[0][3], sb3);

#pragma unroll
        for (int kc = 0; kc < 4; kc++) {
            const int cur = kc & 1, nxt = cur ^ 1;
            if (kc < 3) {
                const uint32_t ko = (kc + 1) * 32;
                ldsm4(a[nxt][0], sa0 + ko); ldsm4(a[nxt][1], sa1 + ko);
                ldsm4(a[nxt][2], sa2 + ko); ldsm4(a[nxt][3], sa3 + ko);
                ldsm4(b[nxt][0], sb0 + ko); ldsm4(b[nxt][1], sb1 + ko);
                ldsm4(b[nxt][2], sb2 + ko); ldsm4(b[nxt][3], sb3 + ko);
            }
#pragma unroll
            for (int mf = 0; mf < 4; mf++)
#pragma unroll
                for (int nf = 0; nf < 8; nf++)
                    mma_bf16(d[mf][nf], a[cur][mf], b[cur][nf >> 1][(nf & 1) * 2],
                             b[cur][nf >> 1][(nf & 1) * 2 + 1]);
        }
    }

    const int rsub = lane >> 2;
    const int csub = (lane & 3) * 2;
#pragma unroll
    for (int mf = 0; mf < 4; mf++) {
#pragma unroll
        for (int nf = 0; nf < 8; nf++) {
            const int row = m0 + warpM + mf * 16 + rsub;
            const int colL = warpN + nf * 8 + csub;
            const float b0 = biasS[colL], b1 = biasS[colL + 1];
            float2 v0 = make_float2(d[mf][nf][0] + b0, d[mf][nf][1] + b1);
            float2 v1 = make_float2(d[mf][nf][2] + b0, d[mf][nf][3] + b1);
            *reinterpret_cast<float2*>(&C[(size_t)row * DMODEL + n0 + colL]) = v0;
            *reinterpret_cast<float2*>(&C[(size_t)(row + 8) * DMODEL + n0 + colL]) = v1;
        }
    }
}

// ============================================================================
// compute_m_partial: Mpart[s][g] = sum over t in [s*64,(s+1)*64) Kg[t]^T Vg[t]
// grid (32, 32), 256 threads, 4x4 per thread.
// ============================================================================
__global__ __launch_bounds__(256)
void compute_m_partial(const float* __restrict__ Kb, const float* __restrict__ Vb,
                       float* __restrict__ Mpart) {
    const int s = blockIdx.x;
    const int g = blockIdx.y;
    __shared__ float Ks[32][64];
    __shared__ float Vs[32][64];

    const int tid = threadIdx.x;
    const int tx = tid & 15;
    const int ty = tid >> 4;

    const float* Kg = Kb + g * 131072 + s * 64 * 64;
    const float* Vg = Vb + g * 131072 + s * 64 * 64;

    unsigned long long acc[4][2];
#pragma unroll
    for (int i = 0; i < 4; i++) { acc[i][0] = 0ull; acc[i][1] = 0ull; }

    for (int t0 = 0; t0 < 64; t0 += 32) {
#pragma unroll
        for (int sr = 0; sr < 2; sr++) {
            int idx = tid + (sr << 8);
            int tt = idx >> 4;
            int d4 = (idx & 15) << 2;
            *reinterpret_cast<float4*>(&Ks[tt][d4]) =
                *reinterpret_cast<const float4*>(&Kg[(t0 + tt) * 64 + d4]);
            *reinterpret_cast<float4*>(&Vs[tt][d4]) =
                *reinterpret_cast<const float4*>(&Vg[(t0 + tt) * 64 + d4]);
        }
        __syncthreads();
#pragma unroll 8
        for (int tt = 0; tt < 32; tt++) {
            float4 a = *reinterpret_cast<const float4*>(&Ks[tt][ty << 2]);
            float4 b = *reinterpret_cast<const float4*>(&Vs[tt][tx << 2]);
            unsigned long long bq0 = f32x2_pack(b.x, b.y);
            unsigned long long bq1 = f32x2_pack(b.z, b.w);
            float av[4] = {a.x, a.y, a.z, a.w};
#pragma unroll
            for (int i = 0; i < 4; i++) {
                unsigned long long ad = f32x2_dup(av[i]);
                acc[i][0] = f32x2_fma(ad, bq0, acc[i][0]);
                acc[i][1] = f32x2_fma(ad, bq1, acc[i][1]);
            }
        }
        __syncthreads();
    }

#pragma unroll
    for (int i = 0; i < 4; i++) {
        float2 v0 = f32x2_unpack(acc[i][0]);
        float2 v1 = f32x2_unpack(acc[i][1]);
        int d = (ty << 2) + i;
        int dp = tx << 2;
        float4 o = make_float4(v0.x, v0.y, v1.x, v1.y);
        *reinterpret_cast<float4*>(&Mpart[(s * 32 + g) * 4096 + d * 64 + dp]) = o;
    }
}

__global__ __launch_bounds__(256)
void reduce_m(const float* __restrict__ Mpart, float* __restrict__ M) {
    int i = blockIdx.x * 256 + threadIdx.x;
    float acc = 0.f;
#pragma unroll
    for (int s = 0; s < 32; s++) acc += Mpart[s * 131072 + i];
    M[i] = acc * 0.03125f;
}

// ============================================================================
// apply_m: O[r, j*64+d'] = sum_d Q[r, j*64+d] * M[g][d][d'],  g = r/128
// Emits bf16 hi/lo directly (feeds bf16 output GEMM).
// ============================================================================
__global__ __launch_bounds__(256)
void apply_m(const float* __restrict__ Qb, const float* __restrict__ Mb,
             __nv_bfloat16* __restrict__ Oh, __nv_bfloat16* __restrict__ Ol) {
    const int j = blockIdx.x;
    const int g = blockIdx.y;

    __shared__ float Qs[64][128];
    __shared__ float Ms[64][64];

    const int tid = threadIdx.x;
    const int tx = tid & 15;
    const int ty = tid >> 4;

#pragma unroll
    for (int s = 0; s < 4; s++) {
        int idx = tid + (s << 8);
        *reinterpret_cast<float4*>(&Ms[idx >> 4][(idx & 15) << 2]) =
            *reinterpret_cast<const float4*>(&Mb[g * 4096 + idx * 4]);
    }
#pragma unroll
    for (int s = 0; s < 8; s++) {
        int idx = tid + (s << 8);
        int r = idx & 127;
        int d4 = (idx >> 7) << 2;
        float4 v = *reinterpret_cast<const float4*>(
            &Qb[(g * 128 + r) * DMODEL + (j << 6) + d4]);
        Qs[d4 + 0][r] = v.x; Qs[d4 + 1][r] = v.y;
        Qs[d4 + 2][r] = v.z; Qs[d4 + 3][r] = v.w;
    }
    __syncthreads();

    unsigned long long acc[8][2];
#pragma unroll
    for (int i = 0; i < 8; i++) { acc[i][0] = 0ull; acc[i][1] = 0ull; }

#pragma unroll 4
    for (int d = 0; d < 64; d++) {
        float4 a0 = *reinterpret_cast<const float4*>(&Qs[d][ty << 3]);
        float4 a1 = *reinterpret_cast<const float4*>(&Qs[d][(ty << 3) + 4]);
        float4 b = *reinterpret_cast<const float4*>(&Ms[d][tx << 2]);
        unsigned long long bq0 = f32x2_pack(b.x, b.y);
        unsigned long long bq1 = f32x2_pack(b.z, b.w);
        float av[8] = {a0.x, a0.y, a0.z, a0.w, a1.x, a1.y, a1.z, a1.w};
#pragma unroll
        for (int i = 0; i < 8; i++) {
            unsigned long long ad = f32x2_dup(av[i]);
            acc[i][0] = f32x2_fma(ad, bq0, acc[i][0]);
            acc[i][1] = f32x2_fma(ad, bq1, acc[i][1]);
        }
    }

#pragma unroll
    for (int i = 0; i < 8; i++) {
        int r = g * 128 + (ty << 3) + i;
        float2 v0 = f32x2_unpack(acc[i][0]);
        float2 v1 = f32x2_unpack(acc[i][1]);
        float4 o = make_float4(v0.x, v0.y, v1.x, v1.y);
        uint2 hv, lv;
        split4_bf16(o, hv, lv);
        int col = (j << 6) + (tx << 2);
        *reinterpret_cast<uint2*>(&Oh[r * DMODEL + col]) = hv;
        *reinterpret_cast<uint2*>(&Ol[r * DMODEL + col]) = lv;
    }
}

// ============================================================================
extern "C" void kernel_launch(void* const* d_in, const int* in_sizes, int n_in,
                              void* d_out, int out_size) {
    const float* x   = (const float*)d_in[0];
    const float* y   = (const float*)d_in[1];
    const float* q_w = (const float*)d_in[2];
    const float* q_b = (const float*)d_in[3];
    const float* k_w = (const float*)d_in[4];
    const float* k_b = (const float*)d_in[5];
    const float* v_w = (const float*)d_in[6];
    const float* v_b = (const float*)d_in[7];
    const float* o_w = (const float*)d_in[8];
    const float* o_b = (const float*)d_in[9];
    float* out = (float*)d_out;

    float *Qp, *Kp, *Vp, *Mpp, *Mp;
    cudaGetSymbolAddress((void**)&Qp, g_Q);
    cudaGetSymbolAddress((void**)&Kp, g_K);
    cudaGetSymbolAddress((void**)&Vp, g_V);
    cudaGetSymbolAddress((void**)&Mpp, g_Mpart);
    cudaGetSymbolAddress((void**)&Mp, g_M);

    __half *xh, *xl, *yh, *yl, *qwh, *kwh, *vwh;
    __nv_bfloat16 *oh, *ol, *owh, *owl;
    cudaGetSymbolAddress((void**)&xh, g_xh);  cudaGetSymbolAddress((void**)&xl, g_xl);
    cudaGetSymbolAddress((void**)&yh, g_yh);  cudaGetSymbolAddress((void**)&yl, g_yl);
    cudaGetSymbolAddress((void**)&qwh, g_qwh);
    cudaGetSymbolAddress((void**)&kwh, g_kwh);
    cudaGetSymbolAddress((void**)&vwh, g_vwh);
    cudaGetSymbolAddress((void**)&oh, g_oh);  cudaGetSymbolAddress((void**)&ol, g_ol);
    cudaGetSymbolAddress((void**)&owh, g_owh); cudaGetSymbolAddress((void**)&owl, g_owl);

    cudaFuncSetAttribute(gemm_qkv_f16, cudaFuncAttributeMaxDynamicSharedMemorySize,
                         FQ_TOTAL);
    cudaFuncSetAttribute(gemm_out_bf16, cudaFuncAttributeMaxDynamicSharedMemorySize,
                         GS_TOTAL);

    const int n4_act = MROWS * DMODEL / 4;    // 1048576
    const int n4_w = DMODEL * DMODEL / 4;     // 262144

    split_act_f16<<<dim3(n4_act / 256, 2), 256>>>(x, y, xh, xl, yh, yl);
    split_wqkv_f16<<<dim3(n4_w / 256, 3), 256>>>(q_w, k_w, v_w, qwh, kwh, vwh);
    split_ow_bf16<<<n4_w / 256, 256>>>(o_w, owh, owl);

    gemm_qkv_f16<<<dim3(DMODEL / 256, MROWS / 128, 3), 256, FQ_TOTAL>>>(
        xh, xl, yh, yl, qwh, kwh, vwh, q_b, k_b, v_b, Qp, Kp, Vp);

    compute_m_partial<<<dim3(32, 32), 256>>>(Kp, Vp, Mpp);
    reduce_m<<<512, 256>>>(Mpp, Mp);
    apply_m<<<dim3(16, 32), 256>>>(Qp, Mp, oh, ol);

    gemm_out_bf16<<<dim3(DMODEL / 256, MROWS / 128), 256, GS_TOTAL>>>(
        oh, ol, owh, owl, o_b, out);
}